// round 14
// baseline (speedup 1.0000x reference)
#include <cuda_runtime.h>
#include <cuda_fp16.h>
#include <cstdint>

#define N_PTS   65536
#define CHN     256
#define BATCH   8
#define KLEN    256
#define CTXD    768
#define NH      8
#define HD      64
#define HDALL   512
#define NPB     8192

// ---- scratch (static device globals) ----
__device__ __align__(16) __half g_xb[(size_t)N_PTS * CHN];
__device__ __align__(16) __half g_ctxb[(size_t)BATCH * KLEN * CTXD];
__device__ __align__(16) __half g_wq[(size_t)CHN * HDALL];          // pre-scaled by D^-0.5*log2(e)
__device__ __align__(16) __half g_wk[(size_t)CTXD * HDALL];
__device__ __align__(16) __half g_wv[(size_t)CTXD * HDALL];
__device__ __align__(16) __half g_wout[(size_t)HDALL * CHN];
__device__ __align__(16) __half g_q[(size_t)N_PTS * HDALL];                 // log2-scaled Q
__device__ __align__(16) __half g_kvh[2][(size_t)BATCH * NH * KLEN * HD];   // K,V [b][h][k][d]
__device__ __align__(16) __half g_o[(size_t)N_PTS * HDALL];

// ============================================================================
// helpers
// ============================================================================
static __device__ __forceinline__ uint32_t packh(float x, float y) {
    __half2 t = __floats2half2_rn(x, y);
    return *(uint32_t*)&t;
}
static __device__ __forceinline__ uint32_t smaddr(const void* p) {
    return (uint32_t)__cvta_generic_to_shared(p);
}
static __device__ __forceinline__ void ldsm_x4(uint32_t a[4], uint32_t addr) {
    asm volatile("ldmatrix.sync.aligned.m8n8.x4.shared.b16 {%0,%1,%2,%3}, [%4];\n"
                 : "=r"(a[0]), "=r"(a[1]), "=r"(a[2]), "=r"(a[3]) : "r"(addr));
}
static __device__ __forceinline__ void ldsm_x4_t(uint32_t a[4], uint32_t addr) {
    asm volatile("ldmatrix.sync.aligned.m8n8.x4.trans.shared.b16 {%0,%1,%2,%3}, [%4];\n"
                 : "=r"(a[0]), "=r"(a[1]), "=r"(a[2]), "=r"(a[3]) : "r"(addr));
}
static __device__ __forceinline__ void mma_f16(float c[4], const uint32_t a[4],
                                               uint32_t b0, uint32_t b1) {
    asm volatile(
        "mma.sync.aligned.m16n8k16.row.col.f32.f16.f16.f32 "
        "{%0,%1,%2,%3}, {%4,%5,%6,%7}, {%8,%9}, {%0,%1,%2,%3};\n"
        : "+f"(c[0]), "+f"(c[1]), "+f"(c[2]), "+f"(c[3])
        : "r"(a[0]), "r"(a[1]), "r"(a[2]), "r"(a[3]), "r"(b0), "r"(b1));
}
// fp16-accumulate variant (for logits)
static __device__ __forceinline__ void mma_h16(uint32_t c[2], const uint32_t a[4],
                                               uint32_t b0, uint32_t b1) {
    asm volatile(
        "mma.sync.aligned.m16n8k16.row.col.f16.f16.f16.f16 "
        "{%0,%1}, {%2,%3,%4,%5}, {%6,%7}, {%0,%1};\n"
        : "+r"(c[0]), "+r"(c[1])
        : "r"(a[0]), "r"(a[1]), "r"(a[2]), "r"(a[3]), "r"(b0), "r"(b1));
}
static __device__ __forceinline__ uint32_t ex2h(uint32_t s) {
    uint32_t d;
    asm volatile("ex2.approx.f16x2 %0, %1;" : "=r"(d) : "r"(s));
    return d;
}
static __device__ __forceinline__ void cpasync16(uint32_t dst, const void* src) {
    asm volatile("cp.async.cg.shared.global [%0], [%1], 16;\n" :: "r"(dst), "l"(src));
}
static __device__ __forceinline__ void cp_commit() {
    asm volatile("cp.async.commit_group;\n");
}
#define CP_WAIT(n) asm volatile("cp.async.wait_group %0;\n" :: "n"(n))

// ============================================================================
// Kernel 0: fp32 -> fp16 conversions (Wq pre-scaled by D^-0.5 * log2(e))
// ============================================================================
__global__ __launch_bounds__(256) void cvt_kernel(
    const float* __restrict__ xF, const float* __restrict__ ctx,
    const float* __restrict__ Wq, const float* __restrict__ Wk,
    const float* __restrict__ Wv, const float* __restrict__ Wout)
{
    size_t t = (size_t)blockIdx.x * blockDim.x + threadIdx.x;
    size_t nt = (size_t)gridDim.x * blockDim.x;
#define CVT(S, D, N4)                                                      \
    for (size_t i = t; i < (N4); i += nt) {                                \
        float4 f = ((const float4*)(S))[i];                                \
        ((uint2*)(D))[i] = make_uint2(packh(f.x, f.y), packh(f.z, f.w));   \
    }
    CVT(xF,   g_xb,   (size_t)N_PTS * CHN / 4)
    CVT(ctx,  g_ctxb, (size_t)BATCH * KLEN * CTXD / 4)
    CVT(Wk,   g_wk,   (size_t)CTXD * HDALL / 4)
    CVT(Wv,   g_wv,   (size_t)CTXD * HDALL / 4)
    CVT(Wout, g_wout, (size_t)HDALL * CHN / 4)
#undef CVT
    const float SC = 0.125f * 1.44269504f;       // D^-0.5 * log2(e)
    for (size_t i = t; i < (size_t)CHN * HDALL / 4; i += nt) {
        float4 f = ((const float4*)Wq)[i];
        ((uint2*)g_wq)[i] = make_uint2(packh(f.x * SC, f.y * SC),
                                       packh(f.z * SC, f.w * SC));
    }
}

// ============================================================================
// shared GEMM pieces: BM=128 BN=128 BK=64, 3-stage cp.async, 256 threads
// ============================================================================
#define ASTR 72
#define BSTR 136
#define ASZ (128 * ASTR * 2)
#define BSZ (64 * BSTR * 2)
#define GEMM_SMEM (3 * (ASZ + BSZ))

static __device__ __forceinline__ void gemm_stage(
    uint32_t As_b, uint32_t Bs_b, int wm, int wn, int arow, int acol,
    float acc[2][8][4])
{
#pragma unroll
    for (int ks = 0; ks < 4; ks++) {
        uint32_t afr[2][4];
#pragma unroll
        for (int mt = 0; mt < 2; mt++)
            ldsm_x4(afr[mt], As_b + ((wm * 32 + mt * 16 + arow) * ASTR + ks * 16 + acol) * 2);
#pragma unroll
        for (int j2 = 0; j2 < 4; j2++) {
            uint32_t bfr[4];
            ldsm_x4_t(bfr, Bs_b + ((ks * 16 + arow) * BSTR + wn * 64 + j2 * 16 + acol) * 2);
#pragma unroll
            for (int mt = 0; mt < 2; mt++) {
                mma_f16(acc[mt][j2 * 2 + 0], afr[mt], bfr[0], bfr[1]);
                mma_f16(acc[mt][j2 * 2 + 1], afr[mt], bfr[2], bfr[3]);
            }
        }
    }
}

static __device__ __forceinline__ void load_B(
    uint32_t Bs_u, int s, const __half* W, int ldB, int col0, int k0, int tid)
{
    uint32_t base = Bs_u + s * BSZ;
#pragma unroll
    for (int i = 0; i < 4; i++) {
        int u = tid + i * 256;
        int kk = u >> 4, c8 = (u & 15) * 8;
        cpasync16(base + (kk * BSTR + c8) * 2, W + (size_t)(k0 + kk) * ldB + col0 + c8);
    }
}

// ============================================================================
// Kernel 1: K/V projection -> g_kvh.  grid (4, 16, 2)
// ============================================================================
__global__ __launch_bounds__(256, 2) void kv_mma()
{
    extern __shared__ __align__(16) char smraw[];
    uint32_t As_u = smaddr(smraw), Bs_u = As_u + 3 * ASZ;

    int tid = threadIdx.x;
    int col0 = blockIdx.x * 128, row0 = blockIdx.y * 128;
    int which = blockIdx.z;
    const __half* W = which ? g_wv : g_wk;

    int w = tid >> 5, lane = tid & 31;
    int wm = w >> 1, wn = w & 1;
    int mat = lane >> 3, lr = lane & 7;
    int arow = lr + (mat & 1) * 8, acol = (mat >> 1) * 8;

    float acc[2][8][4] = {};

#define LOAD_A_CTX(s, k0)                                                          \
    {                                                                              \
        uint32_t base = As_u + (s) * ASZ;                                          \
        _Pragma("unroll")                                                          \
        for (int i = 0; i < 4; i++) {                                              \
            int u = tid + i * 256;                                                 \
            int r = u >> 3, c8 = (u & 7) * 8;                                      \
            cpasync16(base + (r * ASTR + c8) * 2,                                  \
                      g_ctxb + (size_t)(row0 + r) * CTXD + (k0) + c8);             \
        }                                                                          \
    }

    LOAD_A_CTX(0, 0)  load_B(Bs_u, 0, W, HDALL, col0, 0, tid);  cp_commit();
    LOAD_A_CTX(1, 64) load_B(Bs_u, 1, W, HDALL, col0, 64, tid); cp_commit();
    const int KT = CTXD / 64;
#pragma unroll 1
    for (int kt = 0; kt < KT; kt++) {
        if (kt + 1 < KT) { CP_WAIT(1); } else { CP_WAIT(0); }
        __syncthreads();
        int s = kt % 3;
        gemm_stage(As_u + s * ASZ, Bs_u + s * BSZ, wm, wn, arow, acol, acc);
        if (kt + 2 < KT) {
            int sl = (kt + 2) % 3;
            LOAD_A_CTX(sl, (kt + 2) * 64)
            load_B(Bs_u, sl, W, HDALL, col0, (kt + 2) * 64, tid);
            cp_commit();
        }
    }

    int qr = lane >> 2, qc = (lane & 3) * 2;
    __half* outb = g_kvh[which];
#pragma unroll
    for (int mt = 0; mt < 2; mt++) {
        int gr0 = row0 + wm * 32 + mt * 16 + qr;
        int gr1 = gr0 + 8;
#pragma unroll
        for (int nt = 0; nt < 8; nt++) {
            int c = col0 + wn * 64 + nt * 8 + qc;
            int h = c >> 6, d = c & 63;
            int b0 = gr0 >> 8, k0i = gr0 & 255;
            int b1 = gr1 >> 8, k1i = gr1 & 255;
            *(uint32_t*)&outb[((size_t)(b0 * NH + h) * KLEN + k0i) * HD + d] =
                packh(acc[mt][nt][0], acc[mt][nt][1]);
            *(uint32_t*)&outb[((size_t)(b1 * NH + h) * KLEN + k1i) * HD + d] =
                packh(acc[mt][nt][2], acc[mt][nt][3]);
        }
    }
}

// ============================================================================
// Kernel 2: Q projection (gathered).  grid (4, 512); scale pre-folded into Wq
// ============================================================================
__global__ __launch_bounds__(256, 2) void q_mma(const int* __restrict__ perm)
{
    extern __shared__ __align__(16) char smraw[];
    uint32_t As_u = smaddr(smraw), Bs_u = As_u + 3 * ASZ;
    __shared__ int Ridx[128];

    int tid = threadIdx.x;
    int col0 = blockIdx.x * 128, row0 = blockIdx.y * 128;
    if (tid < 128) Ridx[tid] = perm[row0 + tid];
    __syncthreads();

    int w = tid >> 5, lane = tid & 31;
    int wm = w >> 1, wn = w & 1;
    int mat = lane >> 3, lr = lane & 7;
    int arow = lr + (mat & 1) * 8, acol = (mat >> 1) * 8;

    float acc[2][8][4] = {};

#define LOAD_A_GATHER(s, k0)                                                       \
    {                                                                              \
        uint32_t base = As_u + (s) * ASZ;                                          \
        _Pragma("unroll")                                                          \
        for (int i = 0; i < 4; i++) {                                              \
            int u = tid + i * 256;                                                 \
            int r = u >> 3, c8 = (u & 7) * 8;                                      \
            cpasync16(base + (r * ASTR + c8) * 2,                                  \
                      g_xb + (size_t)Ridx[r] * CHN + (k0) + c8);                   \
        }                                                                          \
    }

    LOAD_A_GATHER(0, 0)  load_B(Bs_u, 0, g_wq, HDALL, col0, 0, tid);  cp_commit();
    LOAD_A_GATHER(1, 64) load_B(Bs_u, 1, g_wq, HDALL, col0, 64, tid); cp_commit();
    const int KT = CHN / 64;
#pragma unroll 1
    for (int kt = 0; kt < KT; kt++) {
        if (kt + 1 < KT) { CP_WAIT(1); } else { CP_WAIT(0); }
        __syncthreads();
        int s = kt % 3;
        gemm_stage(As_u + s * ASZ, Bs_u + s * BSZ, wm, wn, arow, acol, acc);
        if (kt + 2 < KT) {
            int sl = (kt + 2) % 3;
            LOAD_A_GATHER(sl, (kt + 2) * 64)
            load_B(Bs_u, sl, g_wq, HDALL, col0, (kt + 2) * 64, tid);
            cp_commit();
        }
    }

    int qr = lane >> 2, qc = (lane & 3) * 2;
#pragma unroll
    for (int mt = 0; mt < 2; mt++) {
        int r = row0 + wm * 32 + mt * 16 + qr;
#pragma unroll
        for (int nt = 0; nt < 8; nt++) {
            int c = col0 + wn * 64 + nt * 8 + qc;
            *(uint32_t*)&g_q[(size_t)r * HDALL + c] =
                packh(acc[mt][nt][0], acc[mt][nt][1]);
            *(uint32_t*)&g_q[(size_t)(r + 8) * HDALL + c] =
                packh(acc[mt][nt][2], acc[mt][nt][3]);
        }
    }
}

// ============================================================================
// Kernel 3: flash attention. 128 thr, 4 warps x 32 rows, 2-stage K/V ring,
// fp16-accum logits -> ex2.f16x2, row-sum via HADD2 on fma pipe (no ones col).
// grid (64, 8, 8), 55296 B smem, 3 CTAs/SM.
// ============================================================================
#define ATSTR 72
#define QSZ   (128 * ATSTR * 2)
#define KVS   (64 * ATSTR * 2)
#define ATTN_SMEM (QSZ + 4 * KVS)

__global__ __launch_bounds__(128, 3) void attn_mma()
{
    extern __shared__ __align__(16) char smraw[];
    uint32_t Qs = smaddr(smraw);
    uint32_t Ks = Qs + QSZ;            // 2 stages
    uint32_t Vs = Ks + 2 * KVS;        // 2 stages

    int qt = blockIdx.x, h = blockIdx.y, b = blockIdx.z;
    int tid = threadIdx.x;
    size_t qrow0 = (size_t)b * NPB + qt * 128;

    const __half* kp = g_kvh[0] + (size_t)(b * NH + h) * KLEN * HD;
    const __half* vp = g_kvh[1] + (size_t)(b * NH + h) * KLEN * HD;

#pragma unroll
    for (int i = 0; i < 8; i++) {
        int u = tid + i * 128;
        int r = u >> 3, c8 = (u & 7) * 8;
        cpasync16(Qs + (r * ATSTR + c8) * 2, g_q + (qrow0 + r) * HDALL + h * HD + c8);
    }
#define LOAD_KV(s, kc)                                                         \
    {                                                                          \
        _Pragma("unroll")                                                      \
        for (int i = 0; i < 4; i++) {                                          \
            int u = tid + i * 128;                                             \
            int r = u >> 3, c8 = (u & 7) * 8;                                  \
            cpasync16(Ks + (s) * KVS + (r * ATSTR + c8) * 2,                   \
                      kp + (size_t)((kc) * 64 + r) * HD + c8);                 \
            cpasync16(Vs + (s) * KVS + (r * ATSTR + c8) * 2,                   \
                      vp + (size_t)((kc) * 64 + r) * HD + c8);                 \
        }                                                                      \
    }
    LOAD_KV(0, 0) cp_commit();
    LOAD_KV(1, 1) cp_commit();

    int w = tid >> 5, lane = tid & 31;
    int mat = lane >> 3, lr = lane & 7;
    int arow = lr + (mat & 1) * 8, acol = (mat >> 1) * 8;
    int brow = lr + (mat >> 1) * 8, bcol = (mat & 1) * 8;
    int row0 = w * 32;

    uint32_t aq[2][4][4];
    float oacc[2][8][4] = {};
    float rs[2][2] = {};                        // row sums: [mt][row qr / qr+8]

#pragma unroll
    for (int kc = 0; kc < 4; kc++) {
        if (kc < 3) { CP_WAIT(1); } else { CP_WAIT(0); }
        __syncthreads();

        if (kc == 0) {
#pragma unroll
            for (int mt = 0; mt < 2; mt++)
#pragma unroll
                for (int kk = 0; kk < 4; kk++)
                    ldsm_x4(aq[mt][kk],
                            Qs + ((row0 + mt * 16 + arow) * ATSTR + kk * 16 + acol) * 2);
        }

        uint32_t kb = Ks + (kc & 1) * KVS, vb = Vs + (kc & 1) * KVS;

#pragma unroll
        for (int t = 0; t < 4; t++) {
            uint32_t s0[2][2] = {}, s1[2][2] = {};
#pragma unroll
            for (int kk = 0; kk < 4; kk++) {
                uint32_t bk[4];
                ldsm_x4(bk, kb + ((t * 16 + brow) * ATSTR + kk * 16 + bcol) * 2);
#pragma unroll
                for (int mt = 0; mt < 2; mt++) {
                    mma_h16(s0[mt], aq[mt][kk], bk[0], bk[1]);
                    mma_h16(s1[mt], aq[mt][kk], bk[2], bk[3]);
                }
            }
            uint32_t pa[2][4];
#pragma unroll
            for (int mt = 0; mt < 2; mt++) {
                pa[mt][0] = ex2h(s0[mt][0]);
                pa[mt][1] = ex2h(s0[mt][1]);
                pa[mt][2] = ex2h(s1[mt][0]);
                pa[mt][3] = ex2h(s1[mt][1]);
                // row sums on the fma/alu pipes (tensor pipe is the scarce one)
                __half2 h01 = __hadd2(*(__half2*)&pa[mt][0], *(__half2*)&pa[mt][2]);
                __half2 h23 = __hadd2(*(__half2*)&pa[mt][1], *(__half2*)&pa[mt][3]);
                float2 f0 = __half22float2(h01);
                float2 f1 = __half22float2(h23);
                rs[mt][0] += f0.x + f0.y;
                rs[mt][1] += f1.x + f1.y;
            }
#pragma unroll
            for (int j2 = 0; j2 < 4; j2++) {
                uint32_t bv[4];
                ldsm_x4_t(bv, vb + ((t * 16 + arow) * ATSTR + j2 * 16 + acol) * 2);
#pragma unroll
                for (int mt = 0; mt < 2; mt++) {
                    mma_f16(oacc[mt][j2 * 2 + 0], pa[mt], bv[0], bv[1]);
                    mma_f16(oacc[mt][j2 * 2 + 1], pa[mt], bv[2], bv[3]);
                }
            }
        }

        if (kc + 2 < 4) {
            __syncthreads();
            LOAD_KV(kc & 1, kc + 2)
            cp_commit();
        }
    }

    int qr = lane >> 2, qc = (lane & 3) * 2;
#pragma unroll
    for (int mt = 0; mt < 2; mt++) {
        // reduce the quad (lanes qr*4 .. qr*4+3 hold disjoint key columns)
        float rsA = rs[mt][0], rsB = rs[mt][1];
        rsA += __shfl_xor_sync(0xffffffffu, rsA, 1);
        rsA += __shfl_xor_sync(0xffffffffu, rsA, 2);
        rsB += __shfl_xor_sync(0xffffffffu, rsB, 1);
        rsB += __shfl_xor_sync(0xffffffffu, rsB, 2);
        float invA = 1.f / rsA, invB = 1.f / rsB;
        size_t rbase = (qrow0 + row0 + mt * 16 + qr) * HDALL + h * HD;
#pragma unroll
        for (int nt = 0; nt < 8; nt++) {
            int d = nt * 8 + qc;
            *(uint32_t*)&g_o[rbase + d] =
                packh(oacc[mt][nt][0] * invA, oacc[mt][nt][1] * invA);
            *(uint32_t*)&g_o[rbase + 8 * HDALL + d] =
                packh(oacc[mt][nt][2] * invB, oacc[mt][nt][3] * invB);
        }
    }
}

// ============================================================================
// Kernel 4: out = scatter(g_o @ Wout) + b_out + xF(fp16).  grid (2, 512)
// ============================================================================
__global__ __launch_bounds__(256, 2) void out_mma(
    const float* __restrict__ bout, const int* __restrict__ perm,
    float* __restrict__ out)
{
    extern __shared__ __align__(16) char smraw[];
    uint32_t As_u = smaddr(smraw), Bs_u = As_u + 3 * ASZ;
    __shared__ int Ridx[128];

    int tid = threadIdx.x;
    int col0 = blockIdx.x * 128, row0 = blockIdx.y * 128;
    if (tid < 128) Ridx[tid] = perm[row0 + tid];
    __syncthreads();

    int w = tid >> 5, lane = tid & 31;
    int wm = w >> 1, wn = w & 1;
    int mat = lane >> 3, lr = lane & 7;
    int arow = lr + (mat & 1) * 8, acol = (mat >> 1) * 8;

    float acc[2][8][4] = {};

#define LOAD_A_GO(s, k0)                                                           \
    {                                                                              \
        uint32_t base = As_u + (s) * ASZ;                                          \
        _Pragma("unroll")                                                          \
        for (int i = 0; i < 4; i++) {                                              \
            int u = tid + i * 256;                                                 \
            int r = u >> 3, c8 = (u & 7) * 8;                                      \
            cpasync16(base + (r * ASTR + c8) * 2,                                  \
                      g_o + (size_t)(row0 + r) * HDALL + (k0) + c8);               \
        }                                                                          \
    }

    LOAD_A_GO(0, 0)  load_B(Bs_u, 0, g_wout, CHN, col0, 0, tid);  cp_commit();
    LOAD_A_GO(1, 64) load_B(Bs_u, 1, g_wout, CHN, col0, 64, tid); cp_commit();
    const int KT = HDALL / 64;
#pragma unroll 1
    for (int kt = 0; kt < KT; kt++) {
        if (kt + 1 < KT) { CP_WAIT(1); } else { CP_WAIT(0); }
        __syncthreads();
        int s = kt % 3;
        gemm_stage(As_u + s * ASZ, Bs_u + s * BSZ, wm, wn, arow, acol, acc);
        if (kt + 2 < KT) {
            int sl = (kt + 2) % 3;
            LOAD_A_GO(sl, (kt + 2) * 64)
            load_B(Bs_u, sl, g_wout, CHN, col0, (kt + 2) * 64, tid);
            cp_commit();
        }
    }

    int qr = lane >> 2, qc = (lane & 3) * 2;
#pragma unroll
    for (int mt = 0; mt < 2; mt++) {
        int gr = wm * 32 + mt * 16 + qr;
        int dst0 = Ridx[gr], dst1 = Ridx[gr + 8];
#pragma unroll
        for (int nt = 0; nt < 8; nt++) {
            int c = col0 + wn * 64 + nt * 8 + qc;
            float2 bb = *(const float2*)&bout[c];
            float2 x0 = __half22float2(*(const __half2*)&g_xb[(size_t)dst0 * CHN + c]);
            float2 x1 = __half22float2(*(const __half2*)&g_xb[(size_t)dst1 * CHN + c]);
            *(float2*)&out[(size_t)dst0 * CHN + c] =
                make_float2(acc[mt][nt][0] + bb.x + x0.x, acc[mt][nt][1] + bb.y + x0.y);
            *(float2*)&out[(size_t)dst1 * CHN + c] =
                make_float2(acc[mt][nt][2] + bb.x + x1.x, acc[mt][nt][3] + bb.y + x1.y);
        }
    }
}

// ============================================================================
extern "C" void kernel_launch(void* const* d_in, const int* in_sizes, int n_in,
                              void* d_out, int out_size)
{
    const float* xF   = (const float*)d_in[0];
    const float* ctx  = (const float*)d_in[1];
    const int*   perm = (const int*)  d_in[2];
    const float* Wq   = (const float*)d_in[3];
    const float* Wk   = (const float*)d_in[4];
    const float* Wv   = (const float*)d_in[5];
    const float* Wout = (const float*)d_in[6];
    const float* bout = (const float*)d_in[7];
    float* out = (float*)d_out;

    cudaFuncSetAttribute(kv_mma,   cudaFuncAttributeMaxDynamicSharedMemorySize, GEMM_SMEM);
    cudaFuncSetAttribute(q_mma,    cudaFuncAttributeMaxDynamicSharedMemorySize, GEMM_SMEM);
    cudaFuncSetAttribute(out_mma,  cudaFuncAttributeMaxDynamicSharedMemorySize, GEMM_SMEM);
    cudaFuncSetAttribute(attn_mma, cudaFuncAttributeMaxDynamicSharedMemorySize, ATTN_SMEM);

    cvt_kernel<<<1024, 256>>>(xF, ctx, Wq, Wk, Wv, Wout);
    kv_mma<<<dim3(HDALL / 128, 2048 / 128, 2), 256, GEMM_SMEM>>>();
    q_mma<<<dim3(HDALL / 128, N_PTS / 128), 256, GEMM_SMEM>>>(perm);
    attn_mma<<<dim3(NPB / 128, NH, BATCH), 128, ATTN_SMEM>>>();
    out_mma<<<dim3(CHN / 128, N_PTS / 128), 256, GEMM_SMEM>>>(bout, perm, out);
}

// round 15
// speedup vs baseline: 1.0041x; 1.0041x over previous
#include <cuda_runtime.h>
#include <cuda_fp16.h>
#include <cstdint>

#define N_PTS   65536
#define CHN     256
#define BATCH   8
#define KLEN    256
#define CTXD    768
#define NH      8
#define HD      64
#define HDALL   512
#define NPB     8192

// ---- scratch (static device globals) ----
__device__ __align__(16) __half g_xb[(size_t)N_PTS * CHN];
__device__ __align__(16) __half g_ctxb[(size_t)BATCH * KLEN * CTXD];
__device__ __align__(16) __half g_wq[(size_t)CHN * HDALL];          // pre-scaled by D^-0.5*log2(e)
__device__ __align__(16) __half g_wk[(size_t)CTXD * HDALL];
__device__ __align__(16) __half g_wv[(size_t)CTXD * HDALL];
__device__ __align__(16) __half g_wout[(size_t)HDALL * CHN];
__device__ __align__(16) __half g_q[(size_t)N_PTS * HDALL];                 // log2-scaled Q
__device__ __align__(16) __half g_kvh[2][(size_t)BATCH * NH * KLEN * HD];   // K,V [b][h][k][d]
__device__ __align__(16) __half g_o[(size_t)N_PTS * HDALL];

// ============================================================================
// helpers
// ============================================================================
static __device__ __forceinline__ uint32_t packh(float x, float y) {
    __half2 t = __floats2half2_rn(x, y);
    return *(uint32_t*)&t;
}
static __device__ __forceinline__ uint32_t smaddr(const void* p) {
    return (uint32_t)__cvta_generic_to_shared(p);
}
static __device__ __forceinline__ void ldsm_x4(uint32_t a[4], uint32_t addr) {
    asm volatile("ldmatrix.sync.aligned.m8n8.x4.shared.b16 {%0,%1,%2,%3}, [%4];\n"
                 : "=r"(a[0]), "=r"(a[1]), "=r"(a[2]), "=r"(a[3]) : "r"(addr));
}
static __device__ __forceinline__ void ldsm_x4_t(uint32_t a[4], uint32_t addr) {
    asm volatile("ldmatrix.sync.aligned.m8n8.x4.trans.shared.b16 {%0,%1,%2,%3}, [%4];\n"
                 : "=r"(a[0]), "=r"(a[1]), "=r"(a[2]), "=r"(a[3]) : "r"(addr));
}
static __device__ __forceinline__ void mma_f16(float c[4], const uint32_t a[4],
                                               uint32_t b0, uint32_t b1) {
    asm volatile(
        "mma.sync.aligned.m16n8k16.row.col.f32.f16.f16.f32 "
        "{%0,%1,%2,%3}, {%4,%5,%6,%7}, {%8,%9}, {%0,%1,%2,%3};\n"
        : "+f"(c[0]), "+f"(c[1]), "+f"(c[2]), "+f"(c[3])
        : "r"(a[0]), "r"(a[1]), "r"(a[2]), "r"(a[3]), "r"(b0), "r"(b1));
}
// fp16-accumulate variant (for logits)
static __device__ __forceinline__ void mma_h16(uint32_t c[2], const uint32_t a[4],
                                               uint32_t b0, uint32_t b1) {
    asm volatile(
        "mma.sync.aligned.m16n8k16.row.col.f16.f16.f16.f16 "
        "{%0,%1}, {%2,%3,%4,%5}, {%6,%7}, {%0,%1};\n"
        : "+r"(c[0]), "+r"(c[1])
        : "r"(a[0]), "r"(a[1]), "r"(a[2]), "r"(a[3]), "r"(b0), "r"(b1));
}
static __device__ __forceinline__ uint32_t ex2h(uint32_t s) {
    uint32_t d;
    asm volatile("ex2.approx.f16x2 %0, %1;" : "=r"(d) : "r"(s));
    return d;
}
static __device__ __forceinline__ void cpasync16(uint32_t dst, const void* src) {
    asm volatile("cp.async.cg.shared.global [%0], [%1], 16;\n" :: "r"(dst), "l"(src));
}
static __device__ __forceinline__ void cp_commit() {
    asm volatile("cp.async.commit_group;\n");
}
#define CP_WAIT(n) asm volatile("cp.async.wait_group %0;\n" :: "n"(n))

// ============================================================================
// Kernel 0: fp32 -> fp16 conversions (Wq pre-scaled by D^-0.5 * log2(e))
// ============================================================================
__global__ __launch_bounds__(256) void cvt_kernel(
    const float* __restrict__ xF, const float* __restrict__ ctx,
    const float* __restrict__ Wq, const float* __restrict__ Wk,
    const float* __restrict__ Wv, const float* __restrict__ Wout)
{
    size_t t = (size_t)blockIdx.x * blockDim.x + threadIdx.x;
    size_t nt = (size_t)gridDim.x * blockDim.x;
#define CVT(S, D, N4)                                                      \
    for (size_t i = t; i < (N4); i += nt) {                                \
        float4 f = ((const float4*)(S))[i];                                \
        ((uint2*)(D))[i] = make_uint2(packh(f.x, f.y), packh(f.z, f.w));   \
    }
    CVT(xF,   g_xb,   (size_t)N_PTS * CHN / 4)
    CVT(ctx,  g_ctxb, (size_t)BATCH * KLEN * CTXD / 4)
    CVT(Wk,   g_wk,   (size_t)CTXD * HDALL / 4)
    CVT(Wv,   g_wv,   (size_t)CTXD * HDALL / 4)
    CVT(Wout, g_wout, (size_t)HDALL * CHN / 4)
#undef CVT
    const float SC = 0.125f * 1.44269504f;       // D^-0.5 * log2(e)
    for (size_t i = t; i < (size_t)CHN * HDALL / 4; i += nt) {
        float4 f = ((const float4*)Wq)[i];
        ((uint2*)g_wq)[i] = make_uint2(packh(f.x * SC, f.y * SC),
                                       packh(f.z * SC, f.w * SC));
    }
}

// ============================================================================
// shared GEMM pieces: BM=128 BN=128 BK=64, 3-stage cp.async, 256 threads
// ============================================================================
#define ASTR 72
#define BSTR 136
#define ASZ (128 * ASTR * 2)
#define BSZ (64 * BSTR * 2)
#define GEMM_SMEM (3 * (ASZ + BSZ))

static __device__ __forceinline__ void gemm_stage(
    uint32_t As_b, uint32_t Bs_b, int wm, int wn, int arow, int acol,
    float acc[2][8][4])
{
#pragma unroll
    for (int ks = 0; ks < 4; ks++) {
        uint32_t afr[2][4];
#pragma unroll
        for (int mt = 0; mt < 2; mt++)
            ldsm_x4(afr[mt], As_b + ((wm * 32 + mt * 16 + arow) * ASTR + ks * 16 + acol) * 2);
#pragma unroll
        for (int j2 = 0; j2 < 4; j2++) {
            uint32_t bfr[4];
            ldsm_x4_t(bfr, Bs_b + ((ks * 16 + arow) * BSTR + wn * 64 + j2 * 16 + acol) * 2);
#pragma unroll
            for (int mt = 0; mt < 2; mt++) {
                mma_f16(acc[mt][j2 * 2 + 0], afr[mt], bfr[0], bfr[1]);
                mma_f16(acc[mt][j2 * 2 + 1], afr[mt], bfr[2], bfr[3]);
            }
        }
    }
}

static __device__ __forceinline__ void load_B(
    uint32_t Bs_u, int s, const __half* W, int ldB, int col0, int k0, int tid)
{
    uint32_t base = Bs_u + s * BSZ;
#pragma unroll
    for (int i = 0; i < 4; i++) {
        int u = tid + i * 256;
        int kk = u >> 4, c8 = (u & 15) * 8;
        cpasync16(base + (kk * BSTR + c8) * 2, W + (size_t)(k0 + kk) * ldB + col0 + c8);
    }
}

// ============================================================================
// Kernel 1: K/V projection -> g_kvh.  grid (4, 16, 2)
// ============================================================================
__global__ __launch_bounds__(256, 2) void kv_mma()
{
    extern __shared__ __align__(16) char smraw[];
    uint32_t As_u = smaddr(smraw), Bs_u = As_u + 3 * ASZ;

    int tid = threadIdx.x;
    int col0 = blockIdx.x * 128, row0 = blockIdx.y * 128;
    int which = blockIdx.z;
    const __half* W = which ? g_wv : g_wk;

    int w = tid >> 5, lane = tid & 31;
    int wm = w >> 1, wn = w & 1;
    int mat = lane >> 3, lr = lane & 7;
    int arow = lr + (mat & 1) * 8, acol = (mat >> 1) * 8;

    float acc[2][8][4] = {};

#define LOAD_A_CTX(s, k0)                                                          \
    {                                                                              \
        uint32_t base = As_u + (s) * ASZ;                                          \
        _Pragma("unroll")                                                          \
        for (int i = 0; i < 4; i++) {                                              \
            int u = tid + i * 256;                                                 \
            int r = u >> 3, c8 = (u & 7) * 8;                                      \
            cpasync16(base + (r * ASTR + c8) * 2,                                  \
                      g_ctxb + (size_t)(row0 + r) * CTXD + (k0) + c8);             \
        }                                                                          \
    }

    LOAD_A_CTX(0, 0)  load_B(Bs_u, 0, W, HDALL, col0, 0, tid);  cp_commit();
    LOAD_A_CTX(1, 64) load_B(Bs_u, 1, W, HDALL, col0, 64, tid); cp_commit();
    const int KT = CTXD / 64;
#pragma unroll 1
    for (int kt = 0; kt < KT; kt++) {
        if (kt + 1 < KT) { CP_WAIT(1); } else { CP_WAIT(0); }
        __syncthreads();
        int s = kt % 3;
        gemm_stage(As_u + s * ASZ, Bs_u + s * BSZ, wm, wn, arow, acol, acc);
        if (kt + 2 < KT) {
            int sl = (kt + 2) % 3;
            LOAD_A_CTX(sl, (kt + 2) * 64)
            load_B(Bs_u, sl, W, HDALL, col0, (kt + 2) * 64, tid);
            cp_commit();
        }
    }

    int qr = lane >> 2, qc = (lane & 3) * 2;
    __half* outb = g_kvh[which];
#pragma unroll
    for (int mt = 0; mt < 2; mt++) {
        int gr0 = row0 + wm * 32 + mt * 16 + qr;
        int gr1 = gr0 + 8;
#pragma unroll
        for (int nt = 0; nt < 8; nt++) {
            int c = col0 + wn * 64 + nt * 8 + qc;
            int h = c >> 6, d = c & 63;
            int b0 = gr0 >> 8, k0i = gr0 & 255;
            int b1 = gr1 >> 8, k1i = gr1 & 255;
            *(uint32_t*)&outb[((size_t)(b0 * NH + h) * KLEN + k0i) * HD + d] =
                packh(acc[mt][nt][0], acc[mt][nt][1]);
            *(uint32_t*)&outb[((size_t)(b1 * NH + h) * KLEN + k1i) * HD + d] =
                packh(acc[mt][nt][2], acc[mt][nt][3]);
        }
    }
}

// ============================================================================
// Kernel 2: Q projection (gathered).  grid (4, 512); scale pre-folded into Wq
// ============================================================================
__global__ __launch_bounds__(256, 2) void q_mma(const int* __restrict__ perm)
{
    extern __shared__ __align__(16) char smraw[];
    uint32_t As_u = smaddr(smraw), Bs_u = As_u + 3 * ASZ;
    __shared__ int Ridx[128];

    int tid = threadIdx.x;
    int col0 = blockIdx.x * 128, row0 = blockIdx.y * 128;
    if (tid < 128) Ridx[tid] = perm[row0 + tid];
    __syncthreads();

    int w = tid >> 5, lane = tid & 31;
    int wm = w >> 1, wn = w & 1;
    int mat = lane >> 3, lr = lane & 7;
    int arow = lr + (mat & 1) * 8, acol = (mat >> 1) * 8;

    float acc[2][8][4] = {};

#define LOAD_A_GATHER(s, k0)                                                       \
    {                                                                              \
        uint32_t base = As_u + (s) * ASZ;                                          \
        _Pragma("unroll")                                                          \
        for (int i = 0; i < 4; i++) {                                              \
            int u = tid + i * 256;                                                 \
            int r = u >> 3, c8 = (u & 7) * 8;                                      \
            cpasync16(base + (r * ASTR + c8) * 2,                                  \
                      g_xb + (size_t)Ridx[r] * CHN + (k0) + c8);                   \
        }                                                                          \
    }

    LOAD_A_GATHER(0, 0)  load_B(Bs_u, 0, g_wq, HDALL, col0, 0, tid);  cp_commit();
    LOAD_A_GATHER(1, 64) load_B(Bs_u, 1, g_wq, HDALL, col0, 64, tid); cp_commit();
    const int KT = CHN / 64;
#pragma unroll 1
    for (int kt = 0; kt < KT; kt++) {
        if (kt + 1 < KT) { CP_WAIT(1); } else { CP_WAIT(0); }
        __syncthreads();
        int s = kt % 3;
        gemm_stage(As_u + s * ASZ, Bs_u + s * BSZ, wm, wn, arow, acol, acc);
        if (kt + 2 < KT) {
            int sl = (kt + 2) % 3;
            LOAD_A_GATHER(sl, (kt + 2) * 64)
            load_B(Bs_u, sl, g_wq, HDALL, col0, (kt + 2) * 64, tid);
            cp_commit();
        }
    }

    int qr = lane >> 2, qc = (lane & 3) * 2;
#pragma unroll
    for (int mt = 0; mt < 2; mt++) {
        int r = row0 + wm * 32 + mt * 16 + qr;
#pragma unroll
        for (int nt = 0; nt < 8; nt++) {
            int c = col0 + wn * 64 + nt * 8 + qc;
            *(uint32_t*)&g_q[(size_t)r * HDALL + c] =
                packh(acc[mt][nt][0], acc[mt][nt][1]);
            *(uint32_t*)&g_q[(size_t)(r + 8) * HDALL + c] =
                packh(acc[mt][nt][2], acc[mt][nt][3]);
        }
    }
}

// ============================================================================
// Kernel 3: flash attention. 128 thr, 4 warps x 32 rows, 2-stage K/V ring,
// fp16-accum logits -> ex2.f16x2, row-sum via HADD2 on fma pipe (no ones col).
// grid (64, 8, 8), 55296 B smem, 3 CTAs/SM.
// ============================================================================
#define ATSTR 72
#define QSZ   (128 * ATSTR * 2)
#define KVS   (64 * ATSTR * 2)
#define ATTN_SMEM (QSZ + 4 * KVS)

__global__ __launch_bounds__(128, 3) void attn_mma()
{
    extern __shared__ __align__(16) char smraw[];
    uint32_t Qs = smaddr(smraw);
    uint32_t Ks = Qs + QSZ;            // 2 stages
    uint32_t Vs = Ks + 2 * KVS;        // 2 stages

    int qt = blockIdx.x, h = blockIdx.y, b = blockIdx.z;
    int tid = threadIdx.x;
    size_t qrow0 = (size_t)b * NPB + qt * 128;

    const __half* kp = g_kvh[0] + (size_t)(b * NH + h) * KLEN * HD;
    const __half* vp = g_kvh[1] + (size_t)(b * NH + h) * KLEN * HD;

#pragma unroll
    for (int i = 0; i < 8; i++) {
        int u = tid + i * 128;
        int r = u >> 3, c8 = (u & 7) * 8;
        cpasync16(Qs + (r * ATSTR + c8) * 2, g_q + (qrow0 + r) * HDALL + h * HD + c8);
    }
#define LOAD_KV(s, kc)                                                         \
    {                                                                          \
        _Pragma("unroll")                                                      \
        for (int i = 0; i < 4; i++) {                                          \
            int u = tid + i * 128;                                             \
            int r = u >> 3, c8 = (u & 7) * 8;                                  \
            cpasync16(Ks + (s) * KVS + (r * ATSTR + c8) * 2,                   \
                      kp + (size_t)((kc) * 64 + r) * HD + c8);                 \
            cpasync16(Vs + (s) * KVS + (r * ATSTR + c8) * 2,                   \
                      vp + (size_t)((kc) * 64 + r) * HD + c8);                 \
        }                                                                      \
    }
    LOAD_KV(0, 0) cp_commit();
    LOAD_KV(1, 1) cp_commit();

    int w = tid >> 5, lane = tid & 31;
    int mat = lane >> 3, lr = lane & 7;
    int arow = lr + (mat & 1) * 8, acol = (mat >> 1) * 8;
    int brow = lr + (mat >> 1) * 8, bcol = (mat & 1) * 8;
    int row0 = w * 32;

    uint32_t aq[2][4][4];
    float oacc[2][8][4] = {};
    float rs[2][2] = {};                        // row sums: [mt][row qr / qr+8]

#pragma unroll
    for (int kc = 0; kc < 4; kc++) {
        if (kc < 3) { CP_WAIT(1); } else { CP_WAIT(0); }
        __syncthreads();

        if (kc == 0) {
#pragma unroll
            for (int mt = 0; mt < 2; mt++)
#pragma unroll
                for (int kk = 0; kk < 4; kk++)
                    ldsm_x4(aq[mt][kk],
                            Qs + ((row0 + mt * 16 + arow) * ATSTR + kk * 16 + acol) * 2);
        }

        uint32_t kb = Ks + (kc & 1) * KVS, vb = Vs + (kc & 1) * KVS;

#pragma unroll
        for (int t = 0; t < 4; t++) {
            uint32_t s0[2][2] = {}, s1[2][2] = {};
#pragma unroll
            for (int kk = 0; kk < 4; kk++) {
                uint32_t bk[4];
                ldsm_x4(bk, kb + ((t * 16 + brow) * ATSTR + kk * 16 + bcol) * 2);
#pragma unroll
                for (int mt = 0; mt < 2; mt++) {
                    mma_h16(s0[mt], aq[mt][kk], bk[0], bk[1]);
                    mma_h16(s1[mt], aq[mt][kk], bk[2], bk[3]);
                }
            }
            uint32_t pa[2][4];
#pragma unroll
            for (int mt = 0; mt < 2; mt++) {
                pa[mt][0] = ex2h(s0[mt][0]);
                pa[mt][1] = ex2h(s0[mt][1]);
                pa[mt][2] = ex2h(s1[mt][0]);
                pa[mt][3] = ex2h(s1[mt][1]);
                // row sums on the fma/alu pipes (tensor pipe is the scarce one)
                __half2 h01 = __hadd2(*(__half2*)&pa[mt][0], *(__half2*)&pa[mt][2]);
                __half2 h23 = __hadd2(*(__half2*)&pa[mt][1], *(__half2*)&pa[mt][3]);
                float2 f0 = __half22float2(h01);
                float2 f1 = __half22float2(h23);
                rs[mt][0] += f0.x + f0.y;
                rs[mt][1] += f1.x + f1.y;
            }
#pragma unroll
            for (int j2 = 0; j2 < 4; j2++) {
                uint32_t bv[4];
                ldsm_x4_t(bv, vb + ((t * 16 + arow) * ATSTR + j2 * 16 + acol) * 2);
#pragma unroll
                for (int mt = 0; mt < 2; mt++) {
                    mma_f16(oacc[mt][j2 * 2 + 0], pa[mt], bv[0], bv[1]);
                    mma_f16(oacc[mt][j2 * 2 + 1], pa[mt], bv[2], bv[3]);
                }
            }
        }

        if (kc + 2 < 4) {
            __syncthreads();
            LOAD_KV(kc & 1, kc + 2)
            cp_commit();
        }
    }

    int qr = lane >> 2, qc = (lane & 3) * 2;
#pragma unroll
    for (int mt = 0; mt < 2; mt++) {
        // reduce the quad (lanes qr*4 .. qr*4+3 hold disjoint key columns)
        float rsA = rs[mt][0], rsB = rs[mt][1];
        rsA += __shfl_xor_sync(0xffffffffu, rsA, 1);
        rsA += __shfl_xor_sync(0xffffffffu, rsA, 2);
        rsB += __shfl_xor_sync(0xffffffffu, rsB, 1);
        rsB += __shfl_xor_sync(0xffffffffu, rsB, 2);
        float invA = 1.f / rsA, invB = 1.f / rsB;
        size_t rbase = (qrow0 + row0 + mt * 16 + qr) * HDALL + h * HD;
#pragma unroll
        for (int nt = 0; nt < 8; nt++) {
            int d = nt * 8 + qc;
            *(uint32_t*)&g_o[rbase + d] =
                packh(oacc[mt][nt][0] * invA, oacc[mt][nt][1] * invA);
            *(uint32_t*)&g_o[rbase + 8 * HDALL + d] =
                packh(oacc[mt][nt][2] * invB, oacc[mt][nt][3] * invB);
        }
    }
}

// ============================================================================
// Kernel 4: out = scatter(g_o @ Wout) + b_out + xF(fp16).  grid (2, 512)
// ============================================================================
__global__ __launch_bounds__(256, 2) void out_mma(
    const float* __restrict__ bout, const int* __restrict__ perm,
    float* __restrict__ out)
{
    extern __shared__ __align__(16) char smraw[];
    uint32_t As_u = smaddr(smraw), Bs_u = As_u + 3 * ASZ;
    __shared__ int Ridx[128];

    int tid = threadIdx.x;
    int col0 = blockIdx.x * 128, row0 = blockIdx.y * 128;
    if (tid < 128) Ridx[tid] = perm[row0 + tid];
    __syncthreads();

    int w = tid >> 5, lane = tid & 31;
    int wm = w >> 1, wn = w & 1;
    int mat = lane >> 3, lr = lane & 7;
    int arow = lr + (mat & 1) * 8, acol = (mat >> 1) * 8;

    float acc[2][8][4] = {};

#define LOAD_A_GO(s, k0)                                                           \
    {                                                                              \
        uint32_t base = As_u + (s) * ASZ;                                          \
        _Pragma("unroll")                                                          \
        for (int i = 0; i < 4; i++) {                                              \
            int u = tid + i * 256;                                                 \
            int r = u >> 3, c8 = (u & 7) * 8;                                      \
            cpasync16(base + (r * ASTR + c8) * 2,                                  \
                      g_o + (size_t)(row0 + r) * HDALL + (k0) + c8);               \
        }                                                                          \
    }

    LOAD_A_GO(0, 0)  load_B(Bs_u, 0, g_wout, CHN, col0, 0, tid);  cp_commit();
    LOAD_A_GO(1, 64) load_B(Bs_u, 1, g_wout, CHN, col0, 64, tid); cp_commit();
    const int KT = HDALL / 64;
#pragma unroll 1
    for (int kt = 0; kt < KT; kt++) {
        if (kt + 1 < KT) { CP_WAIT(1); } else { CP_WAIT(0); }
        __syncthreads();
        int s = kt % 3;
        gemm_stage(As_u + s * ASZ, Bs_u + s * BSZ, wm, wn, arow, acol, acc);
        if (kt + 2 < KT) {
            int sl = (kt + 2) % 3;
            LOAD_A_GO(sl, (kt + 2) * 64)
            load_B(Bs_u, sl, g_wout, CHN, col0, (kt + 2) * 64, tid);
            cp_commit();
        }
    }

    int qr = lane >> 2, qc = (lane & 3) * 2;
#pragma unroll
    for (int mt = 0; mt < 2; mt++) {
        int gr = wm * 32 + mt * 16 + qr;
        int dst0 = Ridx[gr], dst1 = Ridx[gr + 8];
#pragma unroll
        for (int nt = 0; nt < 8; nt++) {
            int c = col0 + wn * 64 + nt * 8 + qc;
            float2 bb = *(const float2*)&bout[c];
            float2 x0 = __half22float2(*(const __half2*)&g_xb[(size_t)dst0 * CHN + c]);
            float2 x1 = __half22float2(*(const __half2*)&g_xb[(size_t)dst1 * CHN + c]);
            *(float2*)&out[(size_t)dst0 * CHN + c] =
                make_float2(acc[mt][nt][0] + bb.x + x0.x, acc[mt][nt][1] + bb.y + x0.y);
            *(float2*)&out[(size_t)dst1 * CHN + c] =
                make_float2(acc[mt][nt][2] + bb.x + x1.x, acc[mt][nt][3] + bb.y + x1.y);
        }
    }
}

// ============================================================================
extern "C" void kernel_launch(void* const* d_in, const int* in_sizes, int n_in,
                              void* d_out, int out_size)
{
    const float* xF   = (const float*)d_in[0];
    const float* ctx  = (const float*)d_in[1];
    const int*   perm = (const int*)  d_in[2];
    const float* Wq   = (const float*)d_in[3];
    const float* Wk   = (const float*)d_in[4];
    const float* Wv   = (const float*)d_in[5];
    const float* Wout = (const float*)d_in[6];
    const float* bout = (const float*)d_in[7];
    float* out = (float*)d_out;

    cudaFuncSetAttribute(kv_mma,   cudaFuncAttributeMaxDynamicSharedMemorySize, GEMM_SMEM);
    cudaFuncSetAttribute(q_mma,    cudaFuncAttributeMaxDynamicSharedMemorySize, GEMM_SMEM);
    cudaFuncSetAttribute(out_mma,  cudaFuncAttributeMaxDynamicSharedMemorySize, GEMM_SMEM);
    cudaFuncSetAttribute(attn_mma, cudaFuncAttributeMaxDynamicSharedMemorySize, ATTN_SMEM);

    cvt_kernel<<<1024, 256>>>(xF, ctx, Wq, Wk, Wv, Wout);
    kv_mma<<<dim3(HDALL / 128, 2048 / 128, 2), 256, GEMM_SMEM>>>();
    q_mma<<<dim3(HDALL / 128, N_PTS / 128), 256, GEMM_SMEM>>>(perm);
    attn_mma<<<dim3(NPB / 128, NH, BATCH), 128, ATTN_SMEM>>>();
    out_mma<<<dim3(CHN / 128, N_PTS / 128), 256, GEMM_SMEM>>>(bout, perm, out);
}

// round 16
// speedup vs baseline: 1.0400x; 1.0358x over previous
#include <cuda_runtime.h>
#include <cuda_fp16.h>
#include <cstdint>

#define N_PTS   65536
#define CHN     256
#define BATCH   8
#define KLEN    256
#define CTXD    768
#define NH      8
#define HD      64
#define HDALL   512
#define NPB     8192

// ---- scratch (static device globals) ----
__device__ __align__(16) __half g_xb[(size_t)N_PTS * CHN];
__device__ __align__(16) __half g_ctxb[(size_t)BATCH * KLEN * CTXD];
__device__ __align__(16) __half g_wq[(size_t)CHN * HDALL];          // pre-scaled by D^-0.5*log2(e)
__device__ __align__(16) __half g_wk[(size_t)CTXD * HDALL];
__device__ __align__(16) __half g_wv[(size_t)CTXD * HDALL];
__device__ __align__(16) __half g_wout[(size_t)HDALL * CHN];
__device__ __align__(16) __half g_q[(size_t)N_PTS * HDALL];                 // log2-scaled Q
__device__ __align__(16) __half g_kvh[2][(size_t)BATCH * NH * KLEN * HD];   // K,V [b][h][k][d]
__device__ __align__(16) __half g_o[(size_t)N_PTS * HDALL];

// ============================================================================
// helpers
// ============================================================================
static __device__ __forceinline__ uint32_t packh(float x, float y) {
    __half2 t = __floats2half2_rn(x, y);
    return *(uint32_t*)&t;
}
static __device__ __forceinline__ uint32_t smaddr(const void* p) {
    return (uint32_t)__cvta_generic_to_shared(p);
}
static __device__ __forceinline__ void ldsm_x4(uint32_t a[4], uint32_t addr) {
    asm volatile("ldmatrix.sync.aligned.m8n8.x4.shared.b16 {%0,%1,%2,%3}, [%4];\n"
                 : "=r"(a[0]), "=r"(a[1]), "=r"(a[2]), "=r"(a[3]) : "r"(addr));
}
static __device__ __forceinline__ void ldsm_x4_t(uint32_t a[4], uint32_t addr) {
    asm volatile("ldmatrix.sync.aligned.m8n8.x4.trans.shared.b16 {%0,%1,%2,%3}, [%4];\n"
                 : "=r"(a[0]), "=r"(a[1]), "=r"(a[2]), "=r"(a[3]) : "r"(addr));
}
static __device__ __forceinline__ void ldsm_x2_t(uint32_t a[2], uint32_t addr) {
    asm volatile("ldmatrix.sync.aligned.m8n8.x2.trans.shared.b16 {%0,%1}, [%2];\n"
                 : "=r"(a[0]), "=r"(a[1]) : "r"(addr));
}
static __device__ __forceinline__ void mma_f16(float c[4], const uint32_t a[4],
                                               uint32_t b0, uint32_t b1) {
    asm volatile(
        "mma.sync.aligned.m16n8k16.row.col.f32.f16.f16.f32 "
        "{%0,%1,%2,%3}, {%4,%5,%6,%7}, {%8,%9}, {%0,%1,%2,%3};\n"
        : "+f"(c[0]), "+f"(c[1]), "+f"(c[2]), "+f"(c[3])
        : "r"(a[0]), "r"(a[1]), "r"(a[2]), "r"(a[3]), "r"(b0), "r"(b1));
}
// fp16-accumulate variant (for logits)
static __device__ __forceinline__ void mma_h16(uint32_t c[2], const uint32_t a[4],
                                               uint32_t b0, uint32_t b1) {
    asm volatile(
        "mma.sync.aligned.m16n8k16.row.col.f16.f16.f16.f16 "
        "{%0,%1}, {%2,%3,%4,%5}, {%6,%7}, {%0,%1};\n"
        : "+r"(c[0]), "+r"(c[1])
        : "r"(a[0]), "r"(a[1]), "r"(a[2]), "r"(a[3]), "r"(b0), "r"(b1));
}
static __device__ __forceinline__ uint32_t ex2h(uint32_t s) {
    uint32_t d;
    asm volatile("ex2.approx.f16x2 %0, %1;" : "=r"(d) : "r"(s));
    return d;
}
static __device__ __forceinline__ void cpasync16(uint32_t dst, const void* src) {
    asm volatile("cp.async.cg.shared.global [%0], [%1], 16;\n" :: "r"(dst), "l"(src));
}
static __device__ __forceinline__ void cp_commit() {
    asm volatile("cp.async.commit_group;\n");
}
#define CP_WAIT(n) asm volatile("cp.async.wait_group %0;\n" :: "n"(n))

// ============================================================================
// Kernel 0: fp32 -> fp16 conversions (Wq pre-scaled by D^-0.5 * log2(e))
// ============================================================================
__global__ __launch_bounds__(256) void cvt_kernel(
    const float* __restrict__ xF, const float* __restrict__ ctx,
    const float* __restrict__ Wq, const float* __restrict__ Wk,
    const float* __restrict__ Wv, const float* __restrict__ Wout)
{
    size_t t = (size_t)blockIdx.x * blockDim.x + threadIdx.x;
    size_t nt = (size_t)gridDim.x * blockDim.x;
#define CVT(S, D, N4)                                                      \
    for (size_t i = t; i < (N4); i += nt) {                                \
        float4 f = ((const float4*)(S))[i];                                \
        ((uint2*)(D))[i] = make_uint2(packh(f.x, f.y), packh(f.z, f.w));   \
    }
    CVT(xF,   g_xb,   (size_t)N_PTS * CHN / 4)
    CVT(ctx,  g_ctxb, (size_t)BATCH * KLEN * CTXD / 4)
    CVT(Wk,   g_wk,   (size_t)CTXD * HDALL / 4)
    CVT(Wv,   g_wv,   (size_t)CTXD * HDALL / 4)
    CVT(Wout, g_wout, (size_t)HDALL * CHN / 4)
#undef CVT
    const float SC = 0.125f * 1.44269504f;       // D^-0.5 * log2(e)
    for (size_t i = t; i < (size_t)CHN * HDALL / 4; i += nt) {
        float4 f = ((const float4*)Wq)[i];
        ((uint2*)g_wq)[i] = make_uint2(packh(f.x * SC, f.y * SC),
                                       packh(f.z * SC, f.w * SC));
    }
}

// ============================================================================
// shared GEMM pieces: BM=128 BN=128 BK=64, 3-stage cp.async, 256 threads
// ============================================================================
#define ASTR 72
#define BSTR 136
#define ASZ (128 * ASTR * 2)
#define BSZ (64 * BSTR * 2)
#define GEMM_SMEM (3 * (ASZ + BSZ))

static __device__ __forceinline__ void gemm_stage(
    uint32_t As_b, uint32_t Bs_b, int wm, int wn, int arow, int acol,
    float acc[2][8][4])
{
#pragma unroll
    for (int ks = 0; ks < 4; ks++) {
        uint32_t afr[2][4];
#pragma unroll
        for (int mt = 0; mt < 2; mt++)
            ldsm_x4(afr[mt], As_b + ((wm * 32 + mt * 16 + arow) * ASTR + ks * 16 + acol) * 2);
#pragma unroll
        for (int j2 = 0; j2 < 4; j2++) {
            uint32_t bfr[4];
            ldsm_x4_t(bfr, Bs_b + ((ks * 16 + arow) * BSTR + wn * 64 + j2 * 16 + acol) * 2);
#pragma unroll
            for (int mt = 0; mt < 2; mt++) {
                mma_f16(acc[mt][j2 * 2 + 0], afr[mt], bfr[0], bfr[1]);
                mma_f16(acc[mt][j2 * 2 + 1], afr[mt], bfr[2], bfr[3]);
            }
        }
    }
}

static __device__ __forceinline__ void load_B(
    uint32_t Bs_u, int s, const __half* W, int ldB, int col0, int k0, int tid)
{
    uint32_t base = Bs_u + s * BSZ;
#pragma unroll
    for (int i = 0; i < 4; i++) {
        int u = tid + i * 256;
        int kk = u >> 4, c8 = (u & 15) * 8;
        cpasync16(base + (kk * BSTR + c8) * 2, W + (size_t)(k0 + kk) * ldB + col0 + c8);
    }
}

// ============================================================================
// Kernel 1: K/V projection -> g_kvh.  grid (4, 16, 2)
// ============================================================================
__global__ __launch_bounds__(256, 2) void kv_mma()
{
    extern __shared__ __align__(16) char smraw[];
    uint32_t As_u = smaddr(smraw), Bs_u = As_u + 3 * ASZ;

    int tid = threadIdx.x;
    int col0 = blockIdx.x * 128, row0 = blockIdx.y * 128;
    int which = blockIdx.z;
    const __half* W = which ? g_wv : g_wk;

    int w = tid >> 5, lane = tid & 31;
    int wm = w >> 1, wn = w & 1;
    int mat = lane >> 3, lr = lane & 7;
    int arow = lr + (mat & 1) * 8, acol = (mat >> 1) * 8;

    float acc[2][8][4] = {};

#define LOAD_A_CTX(s, k0)                                                          \
    {                                                                              \
        uint32_t base = As_u + (s) * ASZ;                                          \
        _Pragma("unroll")                                                          \
        for (int i = 0; i < 4; i++) {                                              \
            int u = tid + i * 256;                                                 \
            int r = u >> 3, c8 = (u & 7) * 8;                                      \
            cpasync16(base + (r * ASTR + c8) * 2,                                  \
                      g_ctxb + (size_t)(row0 + r) * CTXD + (k0) + c8);             \
        }                                                                          \
    }

    LOAD_A_CTX(0, 0)  load_B(Bs_u, 0, W, HDALL, col0, 0, tid);  cp_commit();
    LOAD_A_CTX(1, 64) load_B(Bs_u, 1, W, HDALL, col0, 64, tid); cp_commit();
    const int KT = CTXD / 64;
#pragma unroll 1
    for (int kt = 0; kt < KT; kt++) {
        if (kt + 1 < KT) { CP_WAIT(1); } else { CP_WAIT(0); }
        __syncthreads();
        int s = kt % 3;
        gemm_stage(As_u + s * ASZ, Bs_u + s * BSZ, wm, wn, arow, acol, acc);
        if (kt + 2 < KT) {
            int sl = (kt + 2) % 3;
            LOAD_A_CTX(sl, (kt + 2) * 64)
            load_B(Bs_u, sl, W, HDALL, col0, (kt + 2) * 64, tid);
            cp_commit();
        }
    }

    int qr = lane >> 2, qc = (lane & 3) * 2;
    __half* outb = g_kvh[which];
#pragma unroll
    for (int mt = 0; mt < 2; mt++) {
        int gr0 = row0 + wm * 32 + mt * 16 + qr;
        int gr1 = gr0 + 8;
#pragma unroll
        for (int nt = 0; nt < 8; nt++) {
            int c = col0 + wn * 64 + nt * 8 + qc;
            int h = c >> 6, d = c & 63;
            int b0 = gr0 >> 8, k0i = gr0 & 255;
            int b1 = gr1 >> 8, k1i = gr1 & 255;
            *(uint32_t*)&outb[((size_t)(b0 * NH + h) * KLEN + k0i) * HD + d] =
                packh(acc[mt][nt][0], acc[mt][nt][1]);
            *(uint32_t*)&outb[((size_t)(b1 * NH + h) * KLEN + k1i) * HD + d] =
                packh(acc[mt][nt][2], acc[mt][nt][3]);
        }
    }
}

// ============================================================================
// Kernel 2: Q projection (gathered).  grid (4, 512); scale pre-folded into Wq
// ============================================================================
__global__ __launch_bounds__(256, 2) void q_mma(const int* __restrict__ perm)
{
    extern __shared__ __align__(16) char smraw[];
    uint32_t As_u = smaddr(smraw), Bs_u = As_u + 3 * ASZ;
    __shared__ int Ridx[128];

    int tid = threadIdx.x;
    int col0 = blockIdx.x * 128, row0 = blockIdx.y * 128;
    if (tid < 128) Ridx[tid] = perm[row0 + tid];
    __syncthreads();

    int w = tid >> 5, lane = tid & 31;
    int wm = w >> 1, wn = w & 1;
    int mat = lane >> 3, lr = lane & 7;
    int arow = lr + (mat & 1) * 8, acol = (mat >> 1) * 8;

    float acc[2][8][4] = {};

#define LOAD_A_GATHER(s, k0)                                                       \
    {                                                                              \
        uint32_t base = As_u + (s) * ASZ;                                          \
        _Pragma("unroll")                                                          \
        for (int i = 0; i < 4; i++) {                                              \
            int u = tid + i * 256;                                                 \
            int r = u >> 3, c8 = (u & 7) * 8;                                      \
            cpasync16(base + (r * ASTR + c8) * 2,                                  \
                      g_xb + (size_t)Ridx[r] * CHN + (k0) + c8);                   \
        }                                                                          \
    }

    LOAD_A_GATHER(0, 0)  load_B(Bs_u, 0, g_wq, HDALL, col0, 0, tid);  cp_commit();
    LOAD_A_GATHER(1, 64) load_B(Bs_u, 1, g_wq, HDALL, col0, 64, tid); cp_commit();
    const int KT = CHN / 64;
#pragma unroll 1
    for (int kt = 0; kt < KT; kt++) {
        if (kt + 1 < KT) { CP_WAIT(1); } else { CP_WAIT(0); }
        __syncthreads();
        int s = kt % 3;
        gemm_stage(As_u + s * ASZ, Bs_u + s * BSZ, wm, wn, arow, acol, acc);
        if (kt + 2 < KT) {
            int sl = (kt + 2) % 3;
            LOAD_A_GATHER(sl, (kt + 2) * 64)
            load_B(Bs_u, sl, g_wq, HDALL, col0, (kt + 2) * 64, tid);
            cp_commit();
        }
    }

    int qr = lane >> 2, qc = (lane & 3) * 2;
#pragma unroll
    for (int mt = 0; mt < 2; mt++) {
        int r = row0 + wm * 32 + mt * 16 + qr;
#pragma unroll
        for (int nt = 0; nt < 8; nt++) {
            int c = col0 + wn * 64 + nt * 8 + qc;
            *(uint32_t*)&g_q[(size_t)r * HDALL + c] =
                packh(acc[mt][nt][0], acc[mt][nt][1]);
            *(uint32_t*)&g_q[(size_t)(r + 8) * HDALL + c] =
                packh(acc[mt][nt][2], acc[mt][nt][3]);
        }
    }
}

// ============================================================================
// Kernel 3: flash attention (R8 winner, ones-column rowsum). 128 thr,
// 4 warps x 32 rows, 2-stage K/V ring, fp16-accum logits -> ex2.f16x2.
// grid (64, 8, 8), 55296 B smem, 3 CTAs/SM.
// ============================================================================
#define ATSTR 72
#define QSZ   (128 * ATSTR * 2)
#define KVS   (64 * ATSTR * 2)
#define ATTN_SMEM (QSZ + 4 * KVS)

__global__ __launch_bounds__(128, 3) void attn_mma()
{
    extern __shared__ __align__(16) char smraw[];
    uint32_t Qs = smaddr(smraw);
    uint32_t Ks = Qs + QSZ;            // 2 stages
    uint32_t Vs = Ks + 2 * KVS;        // 2 stages

    int qt = blockIdx.x, h = blockIdx.y, b = blockIdx.z;
    int tid = threadIdx.x;
    size_t qrow0 = (size_t)b * NPB + qt * 128;

    const __half* kp = g_kvh[0] + (size_t)(b * NH + h) * KLEN * HD;
    const __half* vp = g_kvh[1] + (size_t)(b * NH + h) * KLEN * HD;

    // ones column of V (col 64 = 1.0 fp16, 65..71 = 0); 2 stages x 64 rows
    {
        int st = tid >> 6, row = tid & 63;
        *(uint4*)(smraw + QSZ + 2 * KVS + st * KVS + (row * ATSTR + 64) * 2) =
            make_uint4(0x00003C00u, 0u, 0u, 0u);
    }
#pragma unroll
    for (int i = 0; i < 8; i++) {
        int u = tid + i * 128;
        int r = u >> 3, c8 = (u & 7) * 8;
        cpasync16(Qs + (r * ATSTR + c8) * 2, g_q + (qrow0 + r) * HDALL + h * HD + c8);
    }
#define LOAD_KV(s, kc)                                                         \
    {                                                                          \
        _Pragma("unroll")                                                      \
        for (int i = 0; i < 4; i++) {                                          \
            int u = tid + i * 128;                                             \
            int r = u >> 3, c8 = (u & 7) * 8;                                  \
            cpasync16(Ks + (s) * KVS + (r * ATSTR + c8) * 2,                   \
                      kp + (size_t)((kc) * 64 + r) * HD + c8);                 \
            cpasync16(Vs + (s) * KVS + (r * ATSTR + c8) * 2,                   \
                      vp + (size_t)((kc) * 64 + r) * HD + c8);                 \
        }                                                                      \
    }
    LOAD_KV(0, 0) cp_commit();
    LOAD_KV(1, 1) cp_commit();

    int w = tid >> 5, lane = tid & 31;
    int mat = lane >> 3, lr = lane & 7;
    int arow = lr + (mat & 1) * 8, acol = (mat >> 1) * 8;
    int brow = lr + (mat >> 1) * 8, bcol = (mat & 1) * 8;
    int xrow = lr + ((lane >> 3) & 1) * 8;
    int row0 = w * 32;

    uint32_t aq[2][4][4];
    float oacc[2][8][4] = {};
    float oext[2][4] = {};

#pragma unroll
    for (int kc = 0; kc < 4; kc++) {
        if (kc < 3) { CP_WAIT(1); } else { CP_WAIT(0); }
        __syncthreads();

        if (kc == 0) {
#pragma unroll
            for (int mt = 0; mt < 2; mt++)
#pragma unroll
                for (int kk = 0; kk < 4; kk++)
                    ldsm_x4(aq[mt][kk],
                            Qs + ((row0 + mt * 16 + arow) * ATSTR + kk * 16 + acol) * 2);
        }

        uint32_t kb = Ks + (kc & 1) * KVS, vb = Vs + (kc & 1) * KVS;

#pragma unroll
        for (int t = 0; t < 4; t++) {
            uint32_t s0[2][2] = {}, s1[2][2] = {};
#pragma unroll
            for (int kk = 0; kk < 4; kk++) {
                uint32_t bk[4];
                ldsm_x4(bk, kb + ((t * 16 + brow) * ATSTR + kk * 16 + bcol) * 2);
#pragma unroll
                for (int mt = 0; mt < 2; mt++) {
                    mma_h16(s0[mt], aq[mt][kk], bk[0], bk[1]);
                    mma_h16(s1[mt], aq[mt][kk], bk[2], bk[3]);
                }
            }
            uint32_t pa[2][4];
#pragma unroll
            for (int mt = 0; mt < 2; mt++) {
                pa[mt][0] = ex2h(s0[mt][0]);
                pa[mt][1] = ex2h(s0[mt][1]);
                pa[mt][2] = ex2h(s1[mt][0]);
                pa[mt][3] = ex2h(s1[mt][1]);
            }
            uint32_t bvx[2];
            ldsm_x2_t(bvx, vb + ((t * 16 + xrow) * ATSTR + 64) * 2);
#pragma unroll
            for (int j2 = 0; j2 < 4; j2++) {
                uint32_t bv[4];
                ldsm_x4_t(bv, vb + ((t * 16 + arow) * ATSTR + j2 * 16 + acol) * 2);
#pragma unroll
                for (int mt = 0; mt < 2; mt++) {
                    mma_f16(oacc[mt][j2 * 2 + 0], pa[mt], bv[0], bv[1]);
                    mma_f16(oacc[mt][j2 * 2 + 1], pa[mt], bv[2], bv[3]);
                }
            }
#pragma unroll
            for (int mt = 0; mt < 2; mt++)
                mma_f16(oext[mt], pa[mt], bvx[0], bvx[1]);
        }

        if (kc + 2 < 4) {
            __syncthreads();
            LOAD_KV(kc & 1, kc + 2)
            cp_commit();
        }
    }

    int qr = lane >> 2, qc = (lane & 3) * 2;
#pragma unroll
    for (int mt = 0; mt < 2; mt++) {
        float rsA = __shfl_sync(0xffffffffu, oext[mt][0], lane & 28);
        float rsB = __shfl_sync(0xffffffffu, oext[mt][2], lane & 28);
        float invA = 1.f / rsA, invB = 1.f / rsB;
        size_t rbase = (qrow0 + row0 + mt * 16 + qr) * HDALL + h * HD;
#pragma unroll
        for (int nt = 0; nt < 8; nt++) {
            int d = nt * 8 + qc;
            *(uint32_t*)&g_o[rbase + d] =
                packh(oacc[mt][nt][0] * invA, oacc[mt][nt][1] * invA);
            *(uint32_t*)&g_o[rbase + 8 * HDALL + d] =
                packh(oacc[mt][nt][2] * invB, oacc[mt][nt][3] * invB);
        }
    }
}

// ============================================================================
// Kernel 4: out = scatter(g_o @ Wout) + b_out + xF(fp16).  grid (2, 512)
// ============================================================================
__global__ __launch_bounds__(256, 2) void out_mma(
    const float* __restrict__ bout, const int* __restrict__ perm,
    float* __restrict__ out)
{
    extern __shared__ __align__(16) char smraw[];
    uint32_t As_u = smaddr(smraw), Bs_u = As_u + 3 * ASZ;
    __shared__ int Ridx[128];

    int tid = threadIdx.x;
    int col0 = blockIdx.x * 128, row0 = blockIdx.y * 128;
    if (tid < 128) Ridx[tid] = perm[row0 + tid];
    __syncthreads();

    int w = tid >> 5, lane = tid & 31;
    int wm = w >> 1, wn = w & 1;
    int mat = lane >> 3, lr = lane & 7;
    int arow = lr + (mat & 1) * 8, acol = (mat >> 1) * 8;

    float acc[2][8][4] = {};

#define LOAD_A_GO(s, k0)                                                           \
    {                                                                              \
        uint32_t base = As_u + (s) * ASZ;                                          \
        _Pragma("unroll")                                                          \
        for (int i = 0; i < 4; i++) {                                              \
            int u = tid + i * 256;                                                 \
            int r = u >> 3, c8 = (u & 7) * 8;                                      \
            cpasync16(base + (r * ASTR + c8) * 2,                                  \
                      g_o + (size_t)(row0 + r) * HDALL + (k0) + c8);               \
        }                                                                          \
    }

    LOAD_A_GO(0, 0)  load_B(Bs_u, 0, g_wout, CHN, col0, 0, tid);  cp_commit();
    LOAD_A_GO(1, 64) load_B(Bs_u, 1, g_wout, CHN, col0, 64, tid); cp_commit();
    const int KT = HDALL / 64;
#pragma unroll 1
    for (int kt = 0; kt < KT; kt++) {
        if (kt + 1 < KT) { CP_WAIT(1); } else { CP_WAIT(0); }
        __syncthreads();
        int s = kt % 3;
        gemm_stage(As_u + s * ASZ, Bs_u + s * BSZ, wm, wn, arow, acol, acc);
        if (kt + 2 < KT) {
            int sl = (kt + 2) % 3;
            LOAD_A_GO(sl, (kt + 2) * 64)
            load_B(Bs_u, sl, g_wout, CHN, col0, (kt + 2) * 64, tid);
            cp_commit();
        }
    }

    int qr = lane >> 2, qc = (lane & 3) * 2;
#pragma unroll
    for (int mt = 0; mt < 2; mt++) {
        int gr = wm * 32 + mt * 16 + qr;
        int dst0 = Ridx[gr], dst1 = Ridx[gr + 8];
#pragma unroll
        for (int nt = 0; nt < 8; nt++) {
            int c = col0 + wn * 64 + nt * 8 + qc;
            float2 bb = *(const float2*)&bout[c];
            float2 x0 = __half22float2(*(const __half2*)&g_xb[(size_t)dst0 * CHN + c]);
            float2 x1 = __half22float2(*(const __half2*)&g_xb[(size_t)dst1 * CHN + c]);
            *(float2*)&out[(size_t)dst0 * CHN + c] =
                make_float2(acc[mt][nt][0] + bb.x + x0.x, acc[mt][nt][1] + bb.y + x0.y);
            *(float2*)&out[(size_t)dst1 * CHN + c] =
                make_float2(acc[mt][nt][2] + bb.x + x1.x, acc[mt][nt][3] + bb.y + x1.y);
        }
    }
}

// ============================================================================
extern "C" void kernel_launch(void* const* d_in, const int* in_sizes, int n_in,
                              void* d_out, int out_size)
{
    const float* xF   = (const float*)d_in[0];
    const float* ctx  = (const float*)d_in[1];
    const int*   perm = (const int*)  d_in[2];
    const float* Wq   = (const float*)d_in[3];
    const float* Wk   = (const float*)d_in[4];
    const float* Wv   = (const float*)d_in[5];
    const float* Wout = (const float*)d_in[6];
    const float* bout = (const float*)d_in[7];
    float* out = (float*)d_out;

    cudaFuncSetAttribute(kv_mma,   cudaFuncAttributeMaxDynamicSharedMemorySize, GEMM_SMEM);
    cudaFuncSetAttribute(q_mma,    cudaFuncAttributeMaxDynamicSharedMemorySize, GEMM_SMEM);
    cudaFuncSetAttribute(out_mma,  cudaFuncAttributeMaxDynamicSharedMemorySize, GEMM_SMEM);
    cudaFuncSetAttribute(attn_mma, cudaFuncAttributeMaxDynamicSharedMemorySize, ATTN_SMEM);

    cvt_kernel<<<1024, 256>>>(xF, ctx, Wq, Wk, Wv, Wout);
    kv_mma<<<dim3(HDALL / 128, 2048 / 128, 2), 256, GEMM_SMEM>>>();
    q_mma<<<dim3(HDALL / 128, N_PTS / 128), 256, GEMM_SMEM>>>(perm);
    attn_mma<<<dim3(NPB / 128, NH, BATCH), 128, ATTN_SMEM>>>();
    out_mma<<<dim3(CHN / 128, N_PTS / 128), 256, GEMM_SMEM>>>(bout, perm, out);
}

// round 17
// speedup vs baseline: 1.0651x; 1.0241x over previous
#include <cuda_runtime.h>
#include <cuda_fp16.h>
#include <cstdint>

#define N_PTS   65536
#define CHN     256
#define BATCH   8
#define KLEN    256
#define CTXD    768
#define NH      8
#define HD      64
#define HDALL   512
#define NPB     8192

// ---- scratch (static device globals) ----
__device__ __align__(16) __half g_xb[(size_t)N_PTS * CHN];
__device__ __align__(16) __half g_ctxb[(size_t)BATCH * KLEN * CTXD];
__device__ __align__(16) __half g_wq[(size_t)CHN * HDALL];          // pre-scaled by D^-0.5*log2(e)
__device__ __align__(16) __half g_wk[(size_t)CTXD * HDALL];
__device__ __align__(16) __half g_wv[(size_t)CTXD * HDALL];
__device__ __align__(16) __half g_wout[(size_t)HDALL * CHN];
__device__ __align__(16) __half g_q[(size_t)N_PTS * HDALL];                 // log2-scaled Q
__device__ __align__(16) __half g_kvh[2][(size_t)BATCH * NH * KLEN * HD];   // K,V [b][h][k][d]
__device__ __align__(16) __half g_o[(size_t)N_PTS * HDALL];

// ============================================================================
// helpers
// ============================================================================
static __device__ __forceinline__ uint32_t packh(float x, float y) {
    __half2 t = __floats2half2_rn(x, y);
    return *(uint32_t*)&t;
}
static __device__ __forceinline__ uint32_t smaddr(const void* p) {
    return (uint32_t)__cvta_generic_to_shared(p);
}
static __device__ __forceinline__ void ldsm_x4(uint32_t a[4], uint32_t addr) {
    asm volatile("ldmatrix.sync.aligned.m8n8.x4.shared.b16 {%0,%1,%2,%3}, [%4];\n"
                 : "=r"(a[0]), "=r"(a[1]), "=r"(a[2]), "=r"(a[3]) : "r"(addr));
}
static __device__ __forceinline__ void ldsm_x4_t(uint32_t a[4], uint32_t addr) {
    asm volatile("ldmatrix.sync.aligned.m8n8.x4.trans.shared.b16 {%0,%1,%2,%3}, [%4];\n"
                 : "=r"(a[0]), "=r"(a[1]), "=r"(a[2]), "=r"(a[3]) : "r"(addr));
}
static __device__ __forceinline__ void ldsm_x2_t(uint32_t a[2], uint32_t addr) {
    asm volatile("ldmatrix.sync.aligned.m8n8.x2.trans.shared.b16 {%0,%1}, [%2];\n"
                 : "=r"(a[0]), "=r"(a[1]) : "r"(addr));
}
static __device__ __forceinline__ void mma_f16(float c[4], const uint32_t a[4],
                                               uint32_t b0, uint32_t b1) {
    asm volatile(
        "mma.sync.aligned.m16n8k16.row.col.f32.f16.f16.f32 "
        "{%0,%1,%2,%3}, {%4,%5,%6,%7}, {%8,%9}, {%0,%1,%2,%3};\n"
        : "+f"(c[0]), "+f"(c[1]), "+f"(c[2]), "+f"(c[3])
        : "r"(a[0]), "r"(a[1]), "r"(a[2]), "r"(a[3]), "r"(b0), "r"(b1));
}
// fp16-accumulate variant (for logits)
static __device__ __forceinline__ void mma_h16(uint32_t c[2], const uint32_t a[4],
                                               uint32_t b0, uint32_t b1) {
    asm volatile(
        "mma.sync.aligned.m16n8k16.row.col.f16.f16.f16.f16 "
        "{%0,%1}, {%2,%3,%4,%5}, {%6,%7}, {%0,%1};\n"
        : "+r"(c[0]), "+r"(c[1])
        : "r"(a[0]), "r"(a[1]), "r"(a[2]), "r"(a[3]), "r"(b0), "r"(b1));
}
static __device__ __forceinline__ uint32_t ex2h(uint32_t s) {
    uint32_t d;
    asm volatile("ex2.approx.f16x2 %0, %1;" : "=r"(d) : "r"(s));
    return d;
}
static __device__ __forceinline__ void cpasync16(uint32_t dst, const void* src) {
    asm volatile("cp.async.cg.shared.global [%0], [%1], 16;\n" :: "r"(dst), "l"(src));
}
static __device__ __forceinline__ void cp_commit() {
    asm volatile("cp.async.commit_group;\n");
}
#define CP_WAIT(n) asm volatile("cp.async.wait_group %0;\n" :: "n"(n))

// ============================================================================
// Kernel 0: fp32 -> fp16 conversions (Wq pre-scaled by D^-0.5 * log2(e))
// ============================================================================
__global__ __launch_bounds__(256) void cvt_kernel(
    const float* __restrict__ xF, const float* __restrict__ ctx,
    const float* __restrict__ Wq, const float* __restrict__ Wk,
    const float* __restrict__ Wv, const float* __restrict__ Wout)
{
    size_t t = (size_t)blockIdx.x * blockDim.x + threadIdx.x;
    size_t nt = (size_t)gridDim.x * blockDim.x;
#define CVT(S, D, N4)                                                      \
    for (size_t i = t; i < (N4); i += nt) {                                \
        float4 f = ((const float4*)(S))[i];                                \
        ((uint2*)(D))[i] = make_uint2(packh(f.x, f.y), packh(f.z, f.w));   \
    }
    CVT(xF,   g_xb,   (size_t)N_PTS * CHN / 4)
    CVT(ctx,  g_ctxb, (size_t)BATCH * KLEN * CTXD / 4)
    CVT(Wk,   g_wk,   (size_t)CTXD * HDALL / 4)
    CVT(Wv,   g_wv,   (size_t)CTXD * HDALL / 4)
    CVT(Wout, g_wout, (size_t)HDALL * CHN / 4)
#undef CVT
    const float SC = 0.125f * 1.44269504f;       // D^-0.5 * log2(e)
    for (size_t i = t; i < (size_t)CHN * HDALL / 4; i += nt) {
        float4 f = ((const float4*)Wq)[i];
        ((uint2*)g_wq)[i] = make_uint2(packh(f.x * SC, f.y * SC),
                                       packh(f.z * SC, f.w * SC));
    }
}

// ============================================================================
// shared GEMM pieces: BM=128 BN=128 BK=64, 3-stage cp.async, 256 threads
// ============================================================================
#define ASTR 72
#define BSTR 136
#define ASZ (128 * ASTR * 2)
#define BSZ (64 * BSTR * 2)
#define GEMM_SMEM (3 * (ASZ + BSZ))

static __device__ __forceinline__ void gemm_stage(
    uint32_t As_b, uint32_t Bs_b, int wm, int wn, int arow, int acol,
    float acc[2][8][4])
{
#pragma unroll
    for (int ks = 0; ks < 4; ks++) {
        uint32_t afr[2][4];
#pragma unroll
        for (int mt = 0; mt < 2; mt++)
            ldsm_x4(afr[mt], As_b + ((wm * 32 + mt * 16 + arow) * ASTR + ks * 16 + acol) * 2);
#pragma unroll
        for (int j2 = 0; j2 < 4; j2++) {
            uint32_t bfr[4];
            ldsm_x4_t(bfr, Bs_b + ((ks * 16 + arow) * BSTR + wn * 64 + j2 * 16 + acol) * 2);
#pragma unroll
            for (int mt = 0; mt < 2; mt++) {
                mma_f16(acc[mt][j2 * 2 + 0], afr[mt], bfr[0], bfr[1]);
                mma_f16(acc[mt][j2 * 2 + 1], afr[mt], bfr[2], bfr[3]);
            }
        }
    }
}

static __device__ __forceinline__ void load_B(
    uint32_t Bs_u, int s, const __half* W, int ldB, int col0, int k0, int tid)
{
    uint32_t base = Bs_u + s * BSZ;
#pragma unroll
    for (int i = 0; i < 4; i++) {
        int u = tid + i * 256;
        int kk = u >> 4, c8 = (u & 15) * 8;
        cpasync16(base + (kk * BSTR + c8) * 2, W + (size_t)(k0 + kk) * ldB + col0 + c8);
    }
}

// ============================================================================
// Kernel 1: merged projections.  grid = 128 kv CTAs (first) + 2048 q CTAs.
// kv path: K/V = ctx @ Wk/Wv -> g_kvh (KT=12)
// q path:  g_q = gather(xF) @ Wq      (KT=4, scale pre-folded)
// Both use identical smem layout / warp shape (proven kernels, branch only).
// ============================================================================
#define KV_CTAS 128

__global__ __launch_bounds__(256, 2) void proj_mma(const int* __restrict__ perm)
{
    extern __shared__ __align__(16) char smraw[];
    uint32_t As_u = smaddr(smraw), Bs_u = As_u + 3 * ASZ;
    __shared__ int Ridx[128];

    int tid = threadIdx.x;
    int cta = blockIdx.x;

    int w = tid >> 5, lane = tid & 31;
    int wm = w >> 1, wn = w & 1;
    int mat = lane >> 3, lr = lane & 7;
    int arow = lr + (mat & 1) * 8, acol = (mat >> 1) * 8;
    int qr = lane >> 2, qc = (lane & 3) * 2;

    if (cta < KV_CTAS) {
        // ---------------- kv path ----------------
        int which = cta >> 6;
        int rest = cta & 63;
        int col0 = (rest & 3) * 128, row0 = (rest >> 2) * 128;
        const __half* W = which ? g_wv : g_wk;

        float acc[2][8][4] = {};

#define LOAD_A_CTX(s, k0)                                                          \
    {                                                                              \
        uint32_t base = As_u + (s) * ASZ;                                          \
        _Pragma("unroll")                                                          \
        for (int i = 0; i < 4; i++) {                                              \
            int u = tid + i * 256;                                                 \
            int r = u >> 3, c8 = (u & 7) * 8;                                      \
            cpasync16(base + (r * ASTR + c8) * 2,                                  \
                      g_ctxb + (size_t)(row0 + r) * CTXD + (k0) + c8);             \
        }                                                                          \
    }

        LOAD_A_CTX(0, 0)  load_B(Bs_u, 0, W, HDALL, col0, 0, tid);  cp_commit();
        LOAD_A_CTX(1, 64) load_B(Bs_u, 1, W, HDALL, col0, 64, tid); cp_commit();
        const int KT = CTXD / 64;
#pragma unroll 1
        for (int kt = 0; kt < KT; kt++) {
            if (kt + 1 < KT) { CP_WAIT(1); } else { CP_WAIT(0); }
            __syncthreads();
            int s = kt % 3;
            gemm_stage(As_u + s * ASZ, Bs_u + s * BSZ, wm, wn, arow, acol, acc);
            if (kt + 2 < KT) {
                int sl = (kt + 2) % 3;
                LOAD_A_CTX(sl, (kt + 2) * 64)
                load_B(Bs_u, sl, W, HDALL, col0, (kt + 2) * 64, tid);
                cp_commit();
            }
        }

        __half* outb = g_kvh[which];
#pragma unroll
        for (int mt = 0; mt < 2; mt++) {
            int gr0 = row0 + wm * 32 + mt * 16 + qr;
            int gr1 = gr0 + 8;
#pragma unroll
            for (int nt = 0; nt < 8; nt++) {
                int c = col0 + wn * 64 + nt * 8 + qc;
                int h = c >> 6, d = c & 63;
                int b0 = gr0 >> 8, k0i = gr0 & 255;
                int b1 = gr1 >> 8, k1i = gr1 & 255;
                *(uint32_t*)&outb[((size_t)(b0 * NH + h) * KLEN + k0i) * HD + d] =
                    packh(acc[mt][nt][0], acc[mt][nt][1]);
                *(uint32_t*)&outb[((size_t)(b1 * NH + h) * KLEN + k1i) * HD + d] =
                    packh(acc[mt][nt][2], acc[mt][nt][3]);
            }
        }
    } else {
        // ---------------- q path ----------------
        int idx = cta - KV_CTAS;
        int col0 = (idx & 3) * 128, row0 = (idx >> 2) * 128;

        if (tid < 128) Ridx[tid] = perm[row0 + tid];
        __syncthreads();

        float acc[2][8][4] = {};

#define LOAD_A_GATHER(s, k0)                                                       \
    {                                                                              \
        uint32_t base = As_u + (s) * ASZ;                                          \
        _Pragma("unroll")                                                          \
        for (int i = 0; i < 4; i++) {                                              \
            int u = tid + i * 256;                                                 \
            int r = u >> 3, c8 = (u & 7) * 8;                                      \
            cpasync16(base + (r * ASTR + c8) * 2,                                  \
                      g_xb + (size_t)Ridx[r] * CHN + (k0) + c8);                   \
        }                                                                          \
    }

        LOAD_A_GATHER(0, 0)  load_B(Bs_u, 0, g_wq, HDALL, col0, 0, tid);  cp_commit();
        LOAD_A_GATHER(1, 64) load_B(Bs_u, 1, g_wq, HDALL, col0, 64, tid); cp_commit();
        const int KT = CHN / 64;
#pragma unroll 1
        for (int kt = 0; kt < KT; kt++) {
            if (kt + 1 < KT) { CP_WAIT(1); } else { CP_WAIT(0); }
            __syncthreads();
            int s = kt % 3;
            gemm_stage(As_u + s * ASZ, Bs_u + s * BSZ, wm, wn, arow, acol, acc);
            if (kt + 2 < KT) {
                int sl = (kt + 2) % 3;
                LOAD_A_GATHER(sl, (kt + 2) * 64)
                load_B(Bs_u, sl, g_wq, HDALL, col0, (kt + 2) * 64, tid);
                cp_commit();
            }
        }

#pragma unroll
        for (int mt = 0; mt < 2; mt++) {
            int r = row0 + wm * 32 + mt * 16 + qr;
#pragma unroll
            for (int nt = 0; nt < 8; nt++) {
                int c = col0 + wn * 64 + nt * 8 + qc;
                *(uint32_t*)&g_q[(size_t)r * HDALL + c] =
                    packh(acc[mt][nt][0], acc[mt][nt][1]);
                *(uint32_t*)&g_q[(size_t)(r + 8) * HDALL + c] =
                    packh(acc[mt][nt][2], acc[mt][nt][3]);
            }
        }
    }
}

// ============================================================================
// Kernel 3: flash attention (R8 winner, ones-column rowsum). 128 thr,
// 4 warps x 32 rows, 2-stage K/V ring, fp16-accum logits -> ex2.f16x2.
// grid (64, 8, 8), 55296 B smem, 3 CTAs/SM.
// ============================================================================
#define ATSTR 72
#define QSZ   (128 * ATSTR * 2)
#define KVS   (64 * ATSTR * 2)
#define ATTN_SMEM (QSZ + 4 * KVS)

__global__ __launch_bounds__(128, 3) void attn_mma()
{
    extern __shared__ __align__(16) char smraw[];
    uint32_t Qs = smaddr(smraw);
    uint32_t Ks = Qs + QSZ;            // 2 stages
    uint32_t Vs = Ks + 2 * KVS;        // 2 stages

    int qt = blockIdx.x, h = blockIdx.y, b = blockIdx.z;
    int tid = threadIdx.x;
    size_t qrow0 = (size_t)b * NPB + qt * 128;

    const __half* kp = g_kvh[0] + (size_t)(b * NH + h) * KLEN * HD;
    const __half* vp = g_kvh[1] + (size_t)(b * NH + h) * KLEN * HD;

    // ones column of V (col 64 = 1.0 fp16, 65..71 = 0); 2 stages x 64 rows
    {
        int st = tid >> 6, row = tid & 63;
        *(uint4*)(smraw + QSZ + 2 * KVS + st * KVS + (row * ATSTR + 64) * 2) =
            make_uint4(0x00003C00u, 0u, 0u, 0u);
    }
#pragma unroll
    for (int i = 0; i < 8; i++) {
        int u = tid + i * 128;
        int r = u >> 3, c8 = (u & 7) * 8;
        cpasync16(Qs + (r * ATSTR + c8) * 2, g_q + (qrow0 + r) * HDALL + h * HD + c8);
    }
#define LOAD_KV(s, kc)                                                         \
    {                                                                          \
        _Pragma("unroll")                                                      \
        for (int i = 0; i < 4; i++) {                                          \
            int u = tid + i * 128;                                             \
            int r = u >> 3, c8 = (u & 7) * 8;                                  \
            cpasync16(Ks + (s) * KVS + (r * ATSTR + c8) * 2,                   \
                      kp + (size_t)((kc) * 64 + r) * HD + c8);                 \
            cpasync16(Vs + (s) * KVS + (r * ATSTR + c8) * 2,                   \
                      vp + (size_t)((kc) * 64 + r) * HD + c8);                 \
        }                                                                      \
    }
    LOAD_KV(0, 0) cp_commit();
    LOAD_KV(1, 1) cp_commit();

    int w = tid >> 5, lane = tid & 31;
    int mat = lane >> 3, lr = lane & 7;
    int arow = lr + (mat & 1) * 8, acol = (mat >> 1) * 8;
    int brow = lr + (mat >> 1) * 8, bcol = (mat & 1) * 8;
    int xrow = lr + ((lane >> 3) & 1) * 8;
    int row0 = w * 32;

    uint32_t aq[2][4][4];
    float oacc[2][8][4] = {};
    float oext[2][4] = {};

#pragma unroll
    for (int kc = 0; kc < 4; kc++) {
        if (kc < 3) { CP_WAIT(1); } else { CP_WAIT(0); }
        __syncthreads();

        if (kc == 0) {
#pragma unroll
            for (int mt = 0; mt < 2; mt++)
#pragma unroll
                for (int kk = 0; kk < 4; kk++)
                    ldsm_x4(aq[mt][kk],
                            Qs + ((row0 + mt * 16 + arow) * ATSTR + kk * 16 + acol) * 2);
        }

        uint32_t kb = Ks + (kc & 1) * KVS, vb = Vs + (kc & 1) * KVS;

#pragma unroll
        for (int t = 0; t < 4; t++) {
            uint32_t s0[2][2] = {}, s1[2][2] = {};
#pragma unroll
            for (int kk = 0; kk < 4; kk++) {
                uint32_t bk[4];
                ldsm_x4(bk, kb + ((t * 16 + brow) * ATSTR + kk * 16 + bcol) * 2);
#pragma unroll
                for (int mt = 0; mt < 2; mt++) {
                    mma_h16(s0[mt], aq[mt][kk], bk[0], bk[1]);
                    mma_h16(s1[mt], aq[mt][kk], bk[2], bk[3]);
                }
            }
            uint32_t pa[2][4];
#pragma unroll
            for (int mt = 0; mt < 2; mt++) {
                pa[mt][0] = ex2h(s0[mt][0]);
                pa[mt][1] = ex2h(s0[mt][1]);
                pa[mt][2] = ex2h(s1[mt][0]);
                pa[mt][3] = ex2h(s1[mt][1]);
            }
            uint32_t bvx[2];
            ldsm_x2_t(bvx, vb + ((t * 16 + xrow) * ATSTR + 64) * 2);
#pragma unroll
            for (int j2 = 0; j2 < 4; j2++) {
                uint32_t bv[4];
                ldsm_x4_t(bv, vb + ((t * 16 + arow) * ATSTR + j2 * 16 + acol) * 2);
#pragma unroll
                for (int mt = 0; mt < 2; mt++) {
                    mma_f16(oacc[mt][j2 * 2 + 0], pa[mt], bv[0], bv[1]);
                    mma_f16(oacc[mt][j2 * 2 + 1], pa[mt], bv[2], bv[3]);
                }
            }
#pragma unroll
            for (int mt = 0; mt < 2; mt++)
                mma_f16(oext[mt], pa[mt], bvx[0], bvx[1]);
        }

        if (kc + 2 < 4) {
            __syncthreads();
            LOAD_KV(kc & 1, kc + 2)
            cp_commit();
        }
    }

    int qr = lane >> 2, qc = (lane & 3) * 2;
#pragma unroll
    for (int mt = 0; mt < 2; mt++) {
        float rsA = __shfl_sync(0xffffffffu, oext[mt][0], lane & 28);
        float rsB = __shfl_sync(0xffffffffu, oext[mt][2], lane & 28);
        float invA = 1.f / rsA, invB = 1.f / rsB;
        size_t rbase = (qrow0 + row0 + mt * 16 + qr) * HDALL + h * HD;
#pragma unroll
        for (int nt = 0; nt < 8; nt++) {
            int d = nt * 8 + qc;
            *(uint32_t*)&g_o[rbase + d] =
                packh(oacc[mt][nt][0] * invA, oacc[mt][nt][1] * invA);
            *(uint32_t*)&g_o[rbase + 8 * HDALL + d] =
                packh(oacc[mt][nt][2] * invB, oacc[mt][nt][3] * invB);
        }
    }
}

// ============================================================================
// Kernel 4: out = scatter(g_o @ Wout) + b_out + xF(fp16).  grid (2, 512)
// ============================================================================
__global__ __launch_bounds__(256, 2) void out_mma(
    const float* __restrict__ bout, const int* __restrict__ perm,
    float* __restrict__ out)
{
    extern __shared__ __align__(16) char smraw[];
    uint32_t As_u = smaddr(smraw), Bs_u = As_u + 3 * ASZ;
    __shared__ int Ridx[128];

    int tid = threadIdx.x;
    int col0 = blockIdx.x * 128, row0 = blockIdx.y * 128;
    if (tid < 128) Ridx[tid] = perm[row0 + tid];
    __syncthreads();

    int w = tid >> 5, lane = tid & 31;
    int wm = w >> 1, wn = w & 1;
    int mat = lane >> 3, lr = lane & 7;
    int arow = lr + (mat & 1) * 8, acol = (mat >> 1) * 8;

    float acc[2][8][4] = {};

#define LOAD_A_GO(s, k0)                                                           \
    {                                                                              \
        uint32_t base = As_u + (s) * ASZ;                                          \
        _Pragma("unroll")                                                          \
        for (int i = 0; i < 4; i++) {                                              \
            int u = tid + i * 256;                                                 \
            int r = u >> 3, c8 = (u & 7) * 8;                                      \
            cpasync16(base + (r * ASTR + c8) * 2,                                  \
                      g_o + (size_t)(row0 + r) * HDALL + (k0) + c8);               \
        }                                                                          \
    }

    LOAD_A_GO(0, 0)  load_B(Bs_u, 0, g_wout, CHN, col0, 0, tid);  cp_commit();
    LOAD_A_GO(1, 64) load_B(Bs_u, 1, g_wout, CHN, col0, 64, tid); cp_commit();
    const int KT = HDALL / 64;
#pragma unroll 1
    for (int kt = 0; kt < KT; kt++) {
        if (kt + 1 < KT) { CP_WAIT(1); } else { CP_WAIT(0); }
        __syncthreads();
        int s = kt % 3;
        gemm_stage(As_u + s * ASZ, Bs_u + s * BSZ, wm, wn, arow, acol, acc);
        if (kt + 2 < KT) {
            int sl = (kt + 2) % 3;
            LOAD_A_GO(sl, (kt + 2) * 64)
            load_B(Bs_u, sl, g_wout, CHN, col0, (kt + 2) * 64, tid);
            cp_commit();
        }
    }

    int qr = lane >> 2, qc = (lane & 3) * 2;
#pragma unroll
    for (int mt = 0; mt < 2; mt++) {
        int gr = wm * 32 + mt * 16 + qr;
        int dst0 = Ridx[gr], dst1 = Ridx[gr + 8];
#pragma unroll
        for (int nt = 0; nt < 8; nt++) {
            int c = col0 + wn * 64 + nt * 8 + qc;
            float2 bb = *(const float2*)&bout[c];
            float2 x0 = __half22float2(*(const __half2*)&g_xb[(size_t)dst0 * CHN + c]);
            float2 x1 = __half22float2(*(const __half2*)&g_xb[(size_t)dst1 * CHN + c]);
            *(float2*)&out[(size_t)dst0 * CHN + c] =
                make_float2(acc[mt][nt][0] + bb.x + x0.x, acc[mt][nt][1] + bb.y + x0.y);
            *(float2*)&out[(size_t)dst1 * CHN + c] =
                make_float2(acc[mt][nt][2] + bb.x + x1.x, acc[mt][nt][3] + bb.y + x1.y);
        }
    }
}

// ============================================================================
extern "C" void kernel_launch(void* const* d_in, const int* in_sizes, int n_in,
                              void* d_out, int out_size)
{
    const float* xF   = (const float*)d_in[0];
    const float* ctx  = (const float*)d_in[1];
    const int*   perm = (const int*)  d_in[2];
    const float* Wq   = (const float*)d_in[3];
    const float* Wk   = (const float*)d_in[4];
    const float* Wv   = (const float*)d_in[5];
    const float* Wout = (const float*)d_in[6];
    const float* bout = (const float*)d_in[7];
    float* out = (float*)d_out;

    cudaFuncSetAttribute(proj_mma, cudaFuncAttributeMaxDynamicSharedMemorySize, GEMM_SMEM);
    cudaFuncSetAttribute(out_mma,  cudaFuncAttributeMaxDynamicSharedMemorySize, GEMM_SMEM);
    cudaFuncSetAttribute(attn_mma, cudaFuncAttributeMaxDynamicSharedMemorySize, ATTN_SMEM);

    cvt_kernel<<<1024, 256>>>(xF, ctx, Wq, Wk, Wv, Wout);
    proj_mma<<<KV_CTAS + (N_PTS / 128) * (HDALL / 128), 256, GEMM_SMEM>>>(perm);
    attn_mma<<<dim3(NPB / 128, NH, BATCH), 128, ATTN_SMEM>>>();
    out_mma<<<dim3(CHN / 128, N_PTS / 128), 256, GEMM_SMEM>>>(bout, perm, out);
}